// round 11
// baseline (speedup 1.0000x reference)
#include <cuda_runtime.h>
#include <cstdint>

#define NN 50000
#define NE 800000
#define NB 64

// ---------------- scratch (device globals: allocation-free) ----------------
__device__ __align__(16) float g_node[NN * 32];
__device__ __align__(16) float g_P[NN * 32];
__device__ __align__(16) float g_Q[NN * 32];
__device__ __align__(16) float g_pvc[NN * 32];
__device__ __align__(16) float g_a[NN * 32];
__device__ int   g_cnt[NN];     // zero-init at load; re-zeroed by scan23 each run
__device__ int   g_off[NN + 1];
__device__ int   g_cur[NN];
__device__ int   g_csr[2 * NE];
__device__ int   g_bsum[NB];

// ---------------- helpers ----------------
__device__ __forceinline__ uint32_t tf32c(float x) {
    uint32_t r;
    asm("cvt.rna.tf32.f32 %0, %1;" : "=r"(r) : "f"(x));
    return r;
}
__device__ __forceinline__ void mma_tf32(float& d0, float& d1, float& d2, float& d3,
                                         uint32_t a0, uint32_t a1, uint32_t a2, uint32_t a3,
                                         uint32_t b0, uint32_t b1) {
    asm("mma.sync.aligned.m16n8k8.row.col.f32.tf32.tf32.f32 "
        "{%0,%1,%2,%3}, {%4,%5,%6,%7}, {%8,%9}, {%0,%1,%2,%3};"
        : "+f"(d0), "+f"(d1), "+f"(d2), "+f"(d3)
        : "r"(a0), "r"(a1), "r"(a2), "r"(a3), "r"(b0), "r"(b1));
}
__device__ __forceinline__ float sigf(float x) {
    return __fdividef(1.f, 1.f + __expf(-x));
}
__device__ __forceinline__ float tanhfast(float x) {
    float ex = __expf(2.f * x);
    return 1.f - __fdividef(2.f, ex + 1.f);
}

// ---------------- prep kernels ----------------
__global__ void count_kernel(const int* __restrict__ e, int n2e) {
    int i = blockIdx.x * blockDim.x + threadIdx.x;
    if (i < n2e) atomicAdd(&g_cnt[e[i]], 1);
}

__global__ void scan1_kernel(int n, int seg) {
    int b = blockIdx.x;
    int beg = b * seg, end = min(beg + seg, n);
    int tid = threadIdx.x;
    int s = 0;
    for (int i = beg + tid; i < end; i += 256) s += g_cnt[i];
    __shared__ int sm[8];
    int lane = tid & 31, w = tid >> 5;
#pragma unroll
    for (int o = 16; o >= 1; o >>= 1) s += __shfl_down_sync(0xffffffffu, s, o);
    if (lane == 0) sm[w] = s;
    __syncthreads();
    if (tid == 0) {
        int t = 0;
#pragma unroll
        for (int k = 0; k < 8; k++) t += sm[k];
        g_bsum[b] = t;
    }
}

__global__ void scan23_kernel(int n, int seg) {
    int b = blockIdx.x, tid = threadIdx.x;
    __shared__ int s_pre;
    if (tid == 0) {
        int t = 0;
        for (int k = 0; k < b; k++) t += g_bsum[k];
        s_pre = t;
    }
    __syncthreads();
    int beg = b * seg, end = min(beg + seg, n);
    int len = max(end - beg, 0);
    int c = (len + 255) / 256;
    int tb = min(beg + tid * c, end), te = min(tb + c, end);
    int s = 0;
    for (int i = tb; i < te; i++) s += g_cnt[i];
    int lane = tid & 31, w = tid >> 5;
    int v = s;
#pragma unroll
    for (int o = 1; o < 32; o <<= 1) {
        int t = __shfl_up_sync(0xffffffffu, v, o);
        if (lane >= o) v += t;
    }
    __shared__ int wt[8], wpre[8];
    if (lane == 31) wt[w] = v;
    __syncthreads();
    if (tid < 8) {
        int x = wt[tid];
#pragma unroll
        for (int o = 1; o < 8; o <<= 1) {
            int t = __shfl_up_sync(0xffu, x, o);
            if (tid >= o) x += t;
        }
        wpre[tid] = x;
    }
    __syncthreads();
    int excl = (v - s) + (w > 0 ? wpre[w - 1] : 0);
    int run = s_pre + excl;
    for (int i = tb; i < te; i++) {
        g_off[i] = run;
        g_cur[i] = run;
        run += g_cnt[i];
    }
    for (int i = tb; i < te; i++) g_cnt[i] = 0;
    if (b == gridDim.x - 1 && tid == 255) g_off[n] = run;
}

__global__ void scatter_kernel(const int* __restrict__ e, int nE) {
    int i = blockIdx.x * blockDim.x + threadIdx.x;
    if (i >= 2 * nE) return;
    int src = e[i];
    int dst = (i < nE) ? e[i + nE] : e[i - nE];
    int slot = atomicAdd(&g_cur[src], 1);
    g_csr[slot] = dst;
}

// once: node0 = classes@Win.T + bin ; pvc = pos@W1c.T ; P,Q from node0
__global__ void embed_pq_kernel(const float* __restrict__ classes,
                                const float* __restrict__ pos,
                                const float* __restrict__ Win,
                                const float* __restrict__ bin,
                                const float* __restrict__ W1,
                                const float* __restrict__ b1,
                                int n_nodes) {
    int warp = (blockIdx.x * blockDim.x + threadIdx.x) >> 5;
    int j = threadIdx.x & 31;
    if (warp >= n_nodes) return;
    int u = warp;

    float w[16];
#pragma unroll
    for (int k = 0; k < 16; k++) w[k] = Win[j * 16 + k];
    float c = (j < 16) ? classes[u * 16 + j] : 0.f;
    float acc = bin[j];
#pragma unroll
    for (int k = 0; k < 16; k++)
        acc = fmaf(w[k], __shfl_sync(0xffffffffu, c, k), acc);
    g_node[u * 32 + j] = acc;

    float p0 = pos[u * 3 + 0], p1 = pos[u * 3 + 1], p2 = pos[u * 3 + 2];
    float pv = p0 * W1[j * 67 + 64] + p1 * W1[j * 67 + 65] + p2 * W1[j * 67 + 66];
    g_pvc[u * 32 + j] = pv;

    float p = 0.f, q = 0.f;
#pragma unroll
    for (int k = 0; k < 32; k++) {
        float val = __shfl_sync(0xffffffffu, acc, k);
        p = fmaf(W1[j * 67 + k], val, p);
        q = fmaf(W1[j * 67 + 32 + k], val, q);
    }
    g_P[u * 32 + j] = p + b1[j] - pv;
    g_Q[u * 32 + j] = q + pv;
}

// ---------------- message-pass kernel (m16 tiles, paired sub-chunks) ----
__global__ void __launch_bounds__(256, 3) edge_kernel(
        const float* __restrict__ W2, const float* __restrict__ b2,
        int n_nodes) {
    __shared__ float A_s[8][2][16][32];   // 32KB: per-warp tile pair
    int tid = threadIdx.x, wl = tid >> 5, j = tid & 31;

    uint32_t B0[16], B1[16];
#pragma unroll
    for (int kt = 0; kt < 4; kt++)
#pragma unroll
        for (int nt = 0; nt < 4; nt++) {
            int ncol = nt * 8 + (j >> 2);
            int krow = kt * 8 + (j & 3);
            B0[kt * 4 + nt] = tf32c(W2[ncol * 32 + krow]);
            B1[kt * 4 + nt] = tf32c(W2[ncol * 32 + krow + 4]);
        }
    float b2e[4], b2o[4];
#pragma unroll
    for (int nt = 0; nt < 4; nt++) {
        b2e[nt] = b2[nt * 8 + (j & 3) * 2];
        b2o[nt] = b2[nt * 8 + (j & 3) * 2 + 1];
    }
    float bb2 = b2[j];

    uint32_t* AwA = (uint32_t*)A_s[wl][0];
    uint32_t* AwB = (uint32_t*)A_s[wl][1];
    float* smf = &A_s[wl][0][0][0];
    int sub = j & 3;
    int qcol = j >> 2;
    int permj = (j >> 2) + (j & 3) * 8;
    int nw = gridDim.x * 8;

    for (int u = blockIdx.x * 8 + wl; u < n_nodes; u += nw) {
        float pj = g_P[(size_t)u * 32 + j];
        float4 pq4;
        pq4.x = __shfl_sync(0xffffffffu, pj, qcol * 4 + 0);
        pq4.y = __shfl_sync(0xffffffffu, pj, qcol * 4 + 1);
        pq4.z = __shfl_sync(0xffffffffu, pj, qcol * 4 + 2);
        pq4.w = __shfl_sync(0xffffffffu, pj, qcol * 4 + 3);

        int s = g_off[u], e = g_off[u + 1];
        float acc[8];
#pragma unroll
        for (int r = 0; r < 8; r++) acc[r] = 0.f;
        int vcur = (s + j < e) ? g_csr[s + j] : 0;

        for (int base = s; base < e; base += 32) {
            int cnt = min(32, e - base);
            bool hasB = cnt > 16;
            int vnext = (base + 32 + j < e) ? g_csr[base + 32 + j] : 0;
            __syncwarp();
#pragma unroll
            for (int it = 0; it < 4; it++) {
                int row = it * 4 + sub;
                int vv = __shfl_sync(0xffffffffu, vcur, row);
                float4 q = *(const float4*)&g_Q[(size_t)vv * 32 + qcol * 4];
                float h0 = fmaxf(pq4.x + q.x, 0.f);
                float h1 = fmaxf(pq4.y + q.y, 0.f);
                float h2 = fmaxf(pq4.z + q.z, 0.f);
                float h3 = fmaxf(pq4.w + q.w, 0.f);
                if (row >= cnt) { h0 = h1 = h2 = h3 = 0.f; }
                int T0 = ((row >> 3) & 1) + (qcol << 1);
                int bA = T0 * 32;
                int sw = (row & 7) + 2 * T0;
                AwA[bA + ((sw     ) & 31)] = tf32c(h0);
                AwA[bA + ((sw +  8) & 31)] = tf32c(h1);
                AwA[bA + ((sw + 16) & 31)] = tf32c(h2);
                AwA[bA + ((sw + 24) & 31)] = tf32c(h3);
            }
            if (hasB) {
#pragma unroll
                for (int it = 0; it < 4; it++) {
                    int row = it * 4 + sub;
                    int vv = __shfl_sync(0xffffffffu, vcur, 16 + row);
                    float4 q = *(const float4*)&g_Q[(size_t)vv * 32 + qcol * 4];
                    float h0 = fmaxf(pq4.x + q.x, 0.f);
                    float h1 = fmaxf(pq4.y + q.y, 0.f);
                    float h2 = fmaxf(pq4.z + q.z, 0.f);
                    float h3 = fmaxf(pq4.w + q.w, 0.f);
                    if (16 + row >= cnt) { h0 = h1 = h2 = h3 = 0.f; }
                    int T0 = ((row >> 3) & 1) + (qcol << 1);
                    int bA = T0 * 32;
                    int sw = (row & 7) + 2 * T0;
                    AwB[bA + ((sw     ) & 31)] = tf32c(h0);
                    AwB[bA + ((sw +  8) & 31)] = tf32c(h1);
                    AwB[bA + ((sw + 16) & 31)] = tf32c(h2);
                    AwB[bA + ((sw + 24) & 31)] = tf32c(h3);
                }
            }
            __syncwarp();
            {
                uint32_t a[16];
#pragma unroll
                for (int idx = 0; idx < 16; idx++)
                    a[idx] = AwA[idx * 32 + ((permj + 2 * idx) & 31)];
#pragma unroll
                for (int nt = 0; nt < 4; nt++) {
                    float d0 = 0.f, d1 = 0.f, d2 = 0.f, d3 = 0.f;
#pragma unroll
                    for (int kt = 0; kt < 4; kt++)
                        mma_tf32(d0, d1, d2, d3,
                                 a[kt * 4 + 0], a[kt * 4 + 1],
                                 a[kt * 4 + 2], a[kt * 4 + 3],
                                 B0[kt * 4 + nt], B1[kt * 4 + nt]);
                    acc[nt * 2 + 0] += fmaxf(d0 + b2e[nt], 0.f) + fmaxf(d2 + b2e[nt], 0.f);
                    acc[nt * 2 + 1] += fmaxf(d1 + b2o[nt], 0.f) + fmaxf(d3 + b2o[nt], 0.f);
                }
            }
            if (hasB) {
                uint32_t a[16];
#pragma unroll
                for (int idx = 0; idx < 16; idx++)
                    a[idx] = AwB[idx * 32 + ((permj + 2 * idx) & 31)];
#pragma unroll
                for (int nt = 0; nt < 4; nt++) {
                    float d0 = 0.f, d1 = 0.f, d2 = 0.f, d3 = 0.f;
#pragma unroll
                    for (int kt = 0; kt < 4; kt++)
                        mma_tf32(d0, d1, d2, d3,
                                 a[kt * 4 + 0], a[kt * 4 + 1],
                                 a[kt * 4 + 2], a[kt * 4 + 3],
                                 B0[kt * 4 + nt], B1[kt * 4 + nt]);
                    acc[nt * 2 + 0] += fmaxf(d0 + b2e[nt], 0.f) + fmaxf(d2 + b2e[nt], 0.f);
                    acc[nt * 2 + 1] += fmaxf(d1 + b2o[nt], 0.f) + fmaxf(d3 + b2o[nt], 0.f);
                }
            }
            vcur = vnext;
        }

#pragma unroll
        for (int o = 4; o < 32; o <<= 1)
#pragma unroll
            for (int r = 0; r < 8; r++)
                acc[r] += __shfl_xor_sync(0xffffffffu, acc[r], o);
        __syncwarp();
#pragma unroll
        for (int r = 0; r < 8; r++) smf[r * 32 + j] = acc[r];
        __syncwarp();
        float accj = smf[(((j >> 3) << 1) + (j & 1)) * 32 + ((j & 7) >> 1)];

        int deg = e - s;
        int pad = ((deg + 15) & ~15) - deg;
        accj -= (float)pad * fmaxf(bb2, 0.f);

        g_a[(size_t)u * 32 + j] = accj;
    }
}

// ---------------- batched epilogue kernel: node-per-thread, exact fp32 ----
// 256 threads, 1 block/SM cap => 255 regs/thread: the 128 floats of live
// state (S/a/h/nh) fit in registers with NO local-memory spills.
__global__ void __launch_bounds__(256, 1) gru_kernel(
        const float* __restrict__ W1, const float* __restrict__ b1,
        const float* __restrict__ W3, const float* __restrict__ b3,
        const float* __restrict__ Wih, const float* __restrict__ Whh,
        const float* __restrict__ bih, const float* __restrict__ bhh,
        float* __restrict__ out, int write_pq, int n_nodes) {
    __shared__ float sWih[96 * 32];
    __shared__ float sWhh[96 * 32];
    __shared__ float sW3[32 * 32];
    __shared__ float sW1[64 * 32];   // rows 0..31 = W1a, 32..63 = W1b
    __shared__ float sbih[96], sbhh[96], sb3[32], sb1[32];
    int tid = threadIdx.x;
    for (int i = tid; i < 96 * 32; i += 256) { sWih[i] = Wih[i]; sWhh[i] = Whh[i]; }
    for (int i = tid; i < 32 * 32; i += 256) {
        sW3[i] = W3[i];
        sW1[i] = W1[(i >> 5) * 67 + (i & 31)];
        sW1[1024 + i] = W1[(i >> 5) * 67 + 32 + (i & 31)];
    }
    if (tid < 96) { sbih[tid] = bih[tid]; sbhh[tid] = bhh[tid]; }
    if (tid < 32) { sb3[tid] = b3[tid]; sb1[tid] = b1[tid]; }
    __syncthreads();

    int u = blockIdx.x * 256 + tid;
    if (u >= n_nodes) return;

    float deg = (float)(g_off[u + 1] - g_off[u]);

    // a = S @ W3^T + deg*b3  (S scoped so it dies here)
    float a[32];
    {
        float S[32];
        const float4* Sg = (const float4*)&g_a[(size_t)u * 32];
#pragma unroll
        for (int c = 0; c < 8; c++) {
            float4 v = Sg[c];
            S[c * 4] = v.x; S[c * 4 + 1] = v.y; S[c * 4 + 2] = v.z; S[c * 4 + 3] = v.w;
        }
        for (int o = 0; o < 32; o++) {
            const float4* w = (const float4*)&sW3[o * 32];
            float t0 = 0.f, t1 = 0.f;
#pragma unroll
            for (int c = 0; c < 4; c++) {
                float4 wa = w[2 * c], wb = w[2 * c + 1];
                t0 = fmaf(wa.x, S[8 * c + 0], t0); t0 = fmaf(wa.y, S[8 * c + 1], t0);
                t0 = fmaf(wa.z, S[8 * c + 2], t0); t0 = fmaf(wa.w, S[8 * c + 3], t0);
                t1 = fmaf(wb.x, S[8 * c + 4], t1); t1 = fmaf(wb.y, S[8 * c + 5], t1);
                t1 = fmaf(wb.z, S[8 * c + 6], t1); t1 = fmaf(wb.w, S[8 * c + 7], t1);
            }
            a[o] = t0 + t1 + deg * sb3[o];
        }
    }

    float h[32];
    {
        const float4* Hg = (const float4*)&g_node[(size_t)u * 32];
#pragma unroll
        for (int c = 0; c < 8; c++) {
            float4 v = Hg[c];
            h[c * 4] = v.x; h[c * 4 + 1] = v.y; h[c * 4 + 2] = v.z; h[c * 4 + 3] = v.w;
        }
    }

    float nh[32];
    for (int o = 0; o < 32; o++) {
        const float4* wr = (const float4*)&sWih[o * 32];
        const float4* wz = (const float4*)&sWih[(o + 32) * 32];
        const float4* wn = (const float4*)&sWih[(o + 64) * 32];
        const float4* vr = (const float4*)&sWhh[o * 32];
        const float4* vz = (const float4*)&sWhh[(o + 32) * 32];
        const float4* vn = (const float4*)&sWhh[(o + 64) * 32];
        float gir = sbih[o], giz = sbih[o + 32], gin = sbih[o + 64];
        float ghr = sbhh[o], ghz = sbhh[o + 32], ghn = sbhh[o + 64];
#pragma unroll
        for (int c = 0; c < 8; c++) {
            float a0 = a[4 * c], a1 = a[4 * c + 1], a2 = a[4 * c + 2], a3 = a[4 * c + 3];
            float h0 = h[4 * c], h1 = h[4 * c + 1], h2 = h[4 * c + 2], h3 = h[4 * c + 3];
            float4 w;
            w = wr[c]; gir = fmaf(w.x, a0, gir); gir = fmaf(w.y, a1, gir);
                       gir = fmaf(w.z, a2, gir); gir = fmaf(w.w, a3, gir);
            w = wz[c]; giz = fmaf(w.x, a0, giz); giz = fmaf(w.y, a1, giz);
                       giz = fmaf(w.z, a2, giz); giz = fmaf(w.w, a3, giz);
            w = wn[c]; gin = fmaf(w.x, a0, gin); gin = fmaf(w.y, a1, gin);
                       gin = fmaf(w.z, a2, gin); gin = fmaf(w.w, a3, gin);
            w = vr[c]; ghr = fmaf(w.x, h0, ghr); ghr = fmaf(w.y, h1, ghr);
                       ghr = fmaf(w.z, h2, ghr); ghr = fmaf(w.w, h3, ghr);
            w = vz[c]; ghz = fmaf(w.x, h0, ghz); ghz = fmaf(w.y, h1, ghz);
                       ghz = fmaf(w.z, h2, ghz); ghz = fmaf(w.w, h3, ghz);
            w = vn[c]; ghn = fmaf(w.x, h0, ghn); ghn = fmaf(w.y, h1, ghn);
                       ghn = fmaf(w.z, h2, ghn); ghn = fmaf(w.w, h3, ghn);
        }
        float r = sigf(gir + ghr);
        float z = sigf(giz + ghz);
        float nv = tanhfast(gin + r * ghn);
        nh[o] = (1.f - z) * nv + z * h[o];
    }

    {
        float4* Ng = (float4*)&g_node[(size_t)u * 32];
#pragma unroll
        for (int c = 0; c < 8; c++)
            Ng[c] = make_float4(nh[4 * c], nh[4 * c + 1], nh[4 * c + 2], nh[4 * c + 3]);
        if (out) {
            float4* Og = (float4*)&out[(size_t)u * 32];
#pragma unroll
            for (int c = 0; c < 8; c++)
                Og[c] = make_float4(nh[4 * c], nh[4 * c + 1], nh[4 * c + 2], nh[4 * c + 3]);
        }
    }

    if (write_pq) {
        const float4* Vg = (const float4*)&g_pvc[(size_t)u * 32];
        float4* Pg = (float4*)&g_P[(size_t)u * 32];
        float4* Qg = (float4*)&g_Q[(size_t)u * 32];
        for (int cb = 0; cb < 8; cb++) {
            float4 pv = Vg[cb];
            float pr[4], qr[4];
#pragma unroll
            for (int t = 0; t < 4; t++) {
                int jj = cb * 4 + t;
                const float4* wa = (const float4*)&sW1[jj * 32];
                const float4* wb = (const float4*)&sW1[(jj + 32) * 32];
                float p = 0.f, q = 0.f;
#pragma unroll
                for (int c = 0; c < 8; c++) {
                    float4 w1a = wa[c], w1b = wb[c];
                    p = fmaf(w1a.x, nh[4 * c], p);     p = fmaf(w1a.y, nh[4 * c + 1], p);
                    p = fmaf(w1a.z, nh[4 * c + 2], p); p = fmaf(w1a.w, nh[4 * c + 3], p);
                    q = fmaf(w1b.x, nh[4 * c], q);     q = fmaf(w1b.y, nh[4 * c + 1], q);
                    q = fmaf(w1b.z, nh[4 * c + 2], q); q = fmaf(w1b.w, nh[4 * c + 3], q);
                }
                pr[t] = p + sb1[jj];
                qr[t] = q;
            }
            Pg[cb] = make_float4(pr[0] - pv.x, pr[1] - pv.y, pr[2] - pv.z, pr[3] - pv.w);
            Qg[cb] = make_float4(qr[0] + pv.x, qr[1] + pv.y, qr[2] + pv.z, qr[3] + pv.w);
        }
    }
}

// ---------------- launch ----------------
extern "C" void kernel_launch(void* const* d_in, const int* in_sizes, int n_in,
                              void* d_out, int out_size) {
    const float* pos     = (const float*)d_in[0];
    const float* classes = (const float*)d_in[1];
    const int*   edges   = (const int*)d_in[2];
    int wb = (in_sizes[3] == 1) ? 4 : 3;
    const float* Win = (const float*)d_in[wb + 0];
    const float* bin = (const float*)d_in[wb + 1];
    const float* W1  = (const float*)d_in[wb + 2];
    const float* b1  = (const float*)d_in[wb + 3];
    const float* W2  = (const float*)d_in[wb + 4];
    const float* b2  = (const float*)d_in[wb + 5];
    const float* W3  = (const float*)d_in[wb + 6];
    const float* b3  = (const float*)d_in[wb + 7];
    const float* Wih = (const float*)d_in[wb + 8];
    const float* Whh = (const float*)d_in[wb + 9];
    const float* bih = (const float*)d_in[wb + 10];
    const float* bhh = (const float*)d_in[wb + 11];

    int n_nodes = in_sizes[0] / 3;
    int n_edges = in_sizes[2] / 2;
    int n2e = 2 * n_edges;
    float* out = (float*)d_out;
    int seg = (n_nodes + NB - 1) / NB;

    count_kernel<<<(n2e + 255) / 256, 256>>>(edges, n2e);
    scan1_kernel<<<NB, 256>>>(n_nodes, seg);
    scan23_kernel<<<NB, 256>>>(n_nodes, seg);
    scatter_kernel<<<(n2e + 255) / 256, 256>>>(edges, n_edges);
    embed_pq_kernel<<<(n_nodes + 7) / 8, 256>>>(classes, pos, Win, bin, W1, b1,
                                                n_nodes);

    int gru_grid = (n_nodes + 255) / 256;
    for (int it = 0; it < 6; ++it) {
        edge_kernel<<<444, 256>>>(W2, b2, n_nodes);
        gru_kernel<<<gru_grid, 256>>>(
            W1, b1, W3, b3, Wih, Whh, bih, bhh,
            (it == 5) ? out : (float*)nullptr, (it < 5) ? 1 : 0, n_nodes);
    }
}

// round 12
// speedup vs baseline: 1.1470x; 1.1470x over previous
#include <cuda_runtime.h>
#include <cstdint>

#define NN 50000
#define NE 800000
#define NB 64

// ---------------- scratch (device globals: allocation-free) ----------------
__device__ __align__(16) float g_node[NN * 32];
__device__ __align__(16) float g_P[NN * 32];
__device__ __align__(16) float g_Q[NN * 32];
__device__ __align__(16) float g_pvc[NN * 32];
__device__ __align__(16) float g_a[NN * 32];
__device__ int   g_cnt[NN];     // zero-init at load; re-zeroed by scan23 each run
__device__ int   g_off[NN + 1];
__device__ int   g_cur[NN];
__device__ int   g_csr[2 * NE];
__device__ int   g_bsum[NB];

// ---------------- helpers ----------------
__device__ __forceinline__ uint32_t tf32c(float x) {
    uint32_t r;
    asm("cvt.rna.tf32.f32 %0, %1;" : "=r"(r) : "f"(x));
    return r;
}
__device__ __forceinline__ void mma_tf32(float& d0, float& d1, float& d2, float& d3,
                                         uint32_t a0, uint32_t a1, uint32_t a2, uint32_t a3,
                                         uint32_t b0, uint32_t b1) {
    asm("mma.sync.aligned.m16n8k8.row.col.f32.tf32.tf32.f32 "
        "{%0,%1,%2,%3}, {%4,%5,%6,%7}, {%8,%9}, {%0,%1,%2,%3};"
        : "+f"(d0), "+f"(d1), "+f"(d2), "+f"(d3)
        : "r"(a0), "r"(a1), "r"(a2), "r"(a3), "r"(b0), "r"(b1));
}
__device__ __forceinline__ float sigf(float x) {
    return __fdividef(1.f, 1.f + __expf(-x));
}
__device__ __forceinline__ float tanhfast(float x) {
    float ex = __expf(2.f * x);
    return 1.f - __fdividef(2.f, ex + 1.f);
}
__device__ __forceinline__ void cpasync16(uint32_t dst_s, const void* src) {
    asm volatile("cp.async.cg.shared.global [%0], [%1], 16;"
                 :: "r"(dst_s), "l"(src));
}
__device__ __forceinline__ void cpasync_commit() {
    asm volatile("cp.async.commit_group;" ::: "memory");
}
__device__ __forceinline__ void cpasync_wait0() {
    asm volatile("cp.async.wait_group 0;" ::: "memory");
}
__device__ __forceinline__ void cpasync_wait1() {
    asm volatile("cp.async.wait_group 1;" ::: "memory");
}

// ---------------- prep kernels ----------------
__global__ void count_kernel(const int* __restrict__ e, int n2e) {
    int i = blockIdx.x * blockDim.x + threadIdx.x;
    if (i < n2e) atomicAdd(&g_cnt[e[i]], 1);
}

__global__ void scan1_kernel(int n, int seg) {
    int b = blockIdx.x;
    int beg = b * seg, end = min(beg + seg, n);
    int tid = threadIdx.x;
    int s = 0;
    for (int i = beg + tid; i < end; i += 256) s += g_cnt[i];
    __shared__ int sm[8];
    int lane = tid & 31, w = tid >> 5;
#pragma unroll
    for (int o = 16; o >= 1; o >>= 1) s += __shfl_down_sync(0xffffffffu, s, o);
    if (lane == 0) sm[w] = s;
    __syncthreads();
    if (tid == 0) {
        int t = 0;
#pragma unroll
        for (int k = 0; k < 8; k++) t += sm[k];
        g_bsum[b] = t;
    }
}

__global__ void scan23_kernel(int n, int seg) {
    int b = blockIdx.x, tid = threadIdx.x;
    __shared__ int s_pre;
    if (tid == 0) {
        int t = 0;
        for (int k = 0; k < b; k++) t += g_bsum[k];
        s_pre = t;
    }
    __syncthreads();
    int beg = b * seg, end = min(beg + seg, n);
    int len = max(end - beg, 0);
    int c = (len + 255) / 256;
    int tb = min(beg + tid * c, end), te = min(tb + c, end);
    int s = 0;
    for (int i = tb; i < te; i++) s += g_cnt[i];
    int lane = tid & 31, w = tid >> 5;
    int v = s;
#pragma unroll
    for (int o = 1; o < 32; o <<= 1) {
        int t = __shfl_up_sync(0xffffffffu, v, o);
        if (lane >= o) v += t;
    }
    __shared__ int wt[8], wpre[8];
    if (lane == 31) wt[w] = v;
    __syncthreads();
    if (tid < 8) {
        int x = wt[tid];
#pragma unroll
        for (int o = 1; o < 8; o <<= 1) {
            int t = __shfl_up_sync(0xffu, x, o);
            if (tid >= o) x += t;
        }
        wpre[tid] = x;
    }
    __syncthreads();
    int excl = (v - s) + (w > 0 ? wpre[w - 1] : 0);
    int run = s_pre + excl;
    for (int i = tb; i < te; i++) {
        g_off[i] = run;
        g_cur[i] = run;
        run += g_cnt[i];
    }
    for (int i = tb; i < te; i++) g_cnt[i] = 0;
    if (b == gridDim.x - 1 && tid == 255) g_off[n] = run;
}

__global__ void scatter_kernel(const int* __restrict__ e, int nE) {
    int i = blockIdx.x * blockDim.x + threadIdx.x;
    if (i >= 2 * nE) return;
    int src = e[i];
    int dst = (i < nE) ? e[i + nE] : e[i - nE];
    int slot = atomicAdd(&g_cur[src], 1);
    g_csr[slot] = dst;
}

// once: node0 = classes@Win.T + bin ; pvc = pos@W1c.T ; P,Q from node0
__global__ void embed_pq_kernel(const float* __restrict__ classes,
                                const float* __restrict__ pos,
                                const float* __restrict__ Win,
                                const float* __restrict__ bin,
                                const float* __restrict__ W1,
                                const float* __restrict__ b1,
                                int n_nodes) {
    int warp = (blockIdx.x * blockDim.x + threadIdx.x) >> 5;
    int j = threadIdx.x & 31;
    if (warp >= n_nodes) return;
    int u = warp;

    float w[16];
#pragma unroll
    for (int k = 0; k < 16; k++) w[k] = Win[j * 16 + k];
    float c = (j < 16) ? classes[u * 16 + j] : 0.f;
    float acc = bin[j];
#pragma unroll
    for (int k = 0; k < 16; k++)
        acc = fmaf(w[k], __shfl_sync(0xffffffffu, c, k), acc);
    g_node[u * 32 + j] = acc;

    float p0 = pos[u * 3 + 0], p1 = pos[u * 3 + 1], p2 = pos[u * 3 + 2];
    float pv = p0 * W1[j * 67 + 64] + p1 * W1[j * 67 + 65] + p2 * W1[j * 67 + 66];
    g_pvc[u * 32 + j] = pv;

    float p = 0.f, q = 0.f;
#pragma unroll
    for (int k = 0; k < 32; k++) {
        float val = __shfl_sync(0xffffffffu, acc, k);
        p = fmaf(W1[j * 67 + k], val, p);
        q = fmaf(W1[j * 67 + 32 + k], val, q);
    }
    g_P[u * 32 + j] = p + b1[j] - pv;
    g_Q[u * 32 + j] = q + pv;
}

// ---------------- message-pass kernel: cp.async-staged gathers ----------
// dynamic smem (floats): frag = sm[wl*1024 .. +1024) (two m16 tiles),
// stage = sm[8192 + wl*2048 .. +2048) (two 32x32 buffers, XOR-swizzled).
#define EDGE_SMEM_BYTES (24576 * 4)

__global__ void __launch_bounds__(256, 2) edge_kernel(
        const float* __restrict__ W2, const float* __restrict__ b2,
        int n_nodes) {
    extern __shared__ float sm[];
    int tid = threadIdx.x, wl = tid >> 5, j = tid & 31;

    uint32_t B0[16], B1[16];
#pragma unroll
    for (int kt = 0; kt < 4; kt++)
#pragma unroll
        for (int nt = 0; nt < 4; nt++) {
            int ncol = nt * 8 + (j >> 2);
            int krow = kt * 8 + (j & 3);
            B0[kt * 4 + nt] = tf32c(W2[ncol * 32 + krow]);
            B1[kt * 4 + nt] = tf32c(W2[ncol * 32 + krow + 4]);
        }
    float b2e[4], b2o[4];
#pragma unroll
    for (int nt = 0; nt < 4; nt++) {
        b2e[nt] = b2[nt * 8 + (j & 3) * 2];
        b2o[nt] = b2[nt * 8 + (j & 3) * 2 + 1];
    }
    float bb2 = b2[j];

    float* frag  = sm + wl * 1024;          // tile A at +0, tile B at +512
    float* stage = sm + 8192 + wl * 2048;   // buf b at + b*1024
    uint32_t* fragA = (uint32_t*)frag;
    uint32_t* fragB = (uint32_t*)(frag + 512);
    float* smf = frag;

    int jc = j & 7;            // col group 0..7 (16B units)
    int jr = j >> 3;           // row residue 0..3
    int permj = (j >> 2) + (j & 3) * 8;
    int nw = gridDim.x * 8;

    for (int u = blockIdx.x * 8 + wl; u < n_nodes; u += nw) {
        float pj = g_P[(size_t)u * 32 + j];
        float4 pq4;
        pq4.x = __shfl_sync(0xffffffffu, pj, jc * 4 + 0);
        pq4.y = __shfl_sync(0xffffffffu, pj, jc * 4 + 1);
        pq4.z = __shfl_sync(0xffffffffu, pj, jc * 4 + 2);
        pq4.w = __shfl_sync(0xffffffffu, pj, jc * 4 + 3);

        int s = g_off[u], e = g_off[u + 1];
        float acc[8];
#pragma unroll
        for (int r = 0; r < 8; r++) acc[r] = 0.f;

        // prologue: stage pair 0 into buf 0
        int vcur = (s + j < e) ? g_csr[s + j] : 0;
        if (s < e) {
            int cnt0 = min(32, e - s);
#pragma unroll
            for (int k = 0; k < 8; k++) {
                int row = jr + 4 * k;
                int vv = __shfl_sync(0xffffffffu, vcur, row);
                if (row < cnt0) {
                    uint32_t d = (uint32_t)__cvta_generic_to_shared(
                        stage + row * 32 + ((jc ^ (row & 7)) << 2));
                    cpasync16(d, &g_Q[(size_t)vv * 32 + jc * 4]);
                }
            }
            cpasync_commit();
        }
        int vnext = (s + 32 + j < e) ? g_csr[s + 32 + j] : 0;

        int ib = 0;
        for (int base = s; base < e; base += 32, ib ^= 1) {
            int cnt = min(32, e - base);
            bool more = (base + 32) < e;
            // stage pair i+1 into the other buffer
            if (more) {
                int cnt1 = min(32, e - (base + 32));
                float* stg1 = stage + (ib ^ 1) * 1024;
#pragma unroll
                for (int k = 0; k < 8; k++) {
                    int row = jr + 4 * k;
                    int vv = __shfl_sync(0xffffffffu, vnext, row);
                    if (row < cnt1) {
                        uint32_t d = (uint32_t)__cvta_generic_to_shared(
                            stg1 + row * 32 + ((jc ^ (row & 7)) << 2));
                        cpasync16(d, &g_Q[(size_t)vv * 32 + jc * 4]);
                    }
                }
                cpasync_commit();
            }
            int vnn = (base + 64 + j < e) ? g_csr[base + 64 + j] : 0;
            // wait for pair i's staging
            if (more) cpasync_wait1(); else cpasync_wait0();
            __syncwarp();

            float* stg = stage + ib * 1024;
            bool hasB = cnt > 16;
            // ---- pass1 tile A: stage rows 0..15 -> frag A ----
#pragma unroll
            for (int k = 0; k < 4; k++) {
                int row16 = jr + 4 * k;
                int prow = row16;
                float4 q = *(const float4*)&stg[prow * 32 + ((jc ^ (prow & 7)) << 2)];
                float h0 = fmaxf(pq4.x + q.x, 0.f);
                float h1 = fmaxf(pq4.y + q.y, 0.f);
                float h2 = fmaxf(pq4.z + q.z, 0.f);
                float h3 = fmaxf(pq4.w + q.w, 0.f);
                if (prow >= cnt) { h0 = h1 = h2 = h3 = 0.f; }
                int T0 = ((row16 >> 3) & 1) + (jc << 1);
                int bA = T0 * 32;
                int sw = (row16 & 7) + 2 * T0;
                fragA[bA + ((sw     ) & 31)] = tf32c(h0);
                fragA[bA + ((sw +  8) & 31)] = tf32c(h1);
                fragA[bA + ((sw + 16) & 31)] = tf32c(h2);
                fragA[bA + ((sw + 24) & 31)] = tf32c(h3);
            }
            // ---- pass1 tile B: stage rows 16..31 -> frag B ----
            if (hasB) {
#pragma unroll
                for (int k = 0; k < 4; k++) {
                    int row16 = jr + 4 * k;
                    int prow = 16 + row16;
                    float4 q = *(const float4*)&stg[prow * 32 + ((jc ^ (prow & 7)) << 2)];
                    float h0 = fmaxf(pq4.x + q.x, 0.f);
                    float h1 = fmaxf(pq4.y + q.y, 0.f);
                    float h2 = fmaxf(pq4.z + q.z, 0.f);
                    float h3 = fmaxf(pq4.w + q.w, 0.f);
                    if (prow >= cnt) { h0 = h1 = h2 = h3 = 0.f; }
                    int T0 = ((row16 >> 3) & 1) + (jc << 1);
                    int bA = T0 * 32;
                    int sw = (row16 & 7) + 2 * T0;
                    fragB[bA + ((sw     ) & 31)] = tf32c(h0);
                    fragB[bA + ((sw +  8) & 31)] = tf32c(h1);
                    fragB[bA + ((sw + 16) & 31)] = tf32c(h2);
                    fragB[bA + ((sw + 24) & 31)] = tf32c(h3);
                }
            }
            __syncwarp();
            // ---- pass2 tile A ----
            {
                uint32_t a[16];
#pragma unroll
                for (int idx = 0; idx < 16; idx++)
                    a[idx] = fragA[idx * 32 + ((permj + 2 * idx) & 31)];
#pragma unroll
                for (int nt = 0; nt < 4; nt++) {
                    float d0 = 0.f, d1 = 0.f, d2 = 0.f, d3 = 0.f;
#pragma unroll
                    for (int kt = 0; kt < 4; kt++)
                        mma_tf32(d0, d1, d2, d3,
                                 a[kt * 4 + 0], a[kt * 4 + 1],
                                 a[kt * 4 + 2], a[kt * 4 + 3],
                                 B0[kt * 4 + nt], B1[kt * 4 + nt]);
                    acc[nt * 2 + 0] += fmaxf(d0 + b2e[nt], 0.f) + fmaxf(d2 + b2e[nt], 0.f);
                    acc[nt * 2 + 1] += fmaxf(d1 + b2o[nt], 0.f) + fmaxf(d3 + b2o[nt], 0.f);
                }
            }
            // ---- pass2 tile B ----
            if (hasB) {
                uint32_t a[16];
#pragma unroll
                for (int idx = 0; idx < 16; idx++)
                    a[idx] = fragB[idx * 32 + ((permj + 2 * idx) & 31)];
#pragma unroll
                for (int nt = 0; nt < 4; nt++) {
                    float d0 = 0.f, d1 = 0.f, d2 = 0.f, d3 = 0.f;
#pragma unroll
                    for (int kt = 0; kt < 4; kt++)
                        mma_tf32(d0, d1, d2, d3,
                                 a[kt * 4 + 0], a[kt * 4 + 1],
                                 a[kt * 4 + 2], a[kt * 4 + 3],
                                 B0[kt * 4 + nt], B1[kt * 4 + nt]);
                    acc[nt * 2 + 0] += fmaxf(d0 + b2e[nt], 0.f) + fmaxf(d2 + b2e[nt], 0.f);
                    acc[nt * 2 + 1] += fmaxf(d1 + b2o[nt], 0.f) + fmaxf(d3 + b2o[nt], 0.f);
                }
            }
            vnext = vnn;
        }

        // cross-lane reduce + remap to col-per-lane (layout verified round 8)
#pragma unroll
        for (int o = 4; o < 32; o <<= 1)
#pragma unroll
            for (int r = 0; r < 8; r++)
                acc[r] += __shfl_xor_sync(0xffffffffu, acc[r], o);
        __syncwarp();
#pragma unroll
        for (int r = 0; r < 8; r++) smf[r * 32 + j] = acc[r];
        __syncwarp();
        float accj = smf[(((j >> 3) << 1) + (j & 1)) * 32 + ((j & 7) >> 1)];

        int deg = e - s;
        int pad = ((deg + 15) & ~15) - deg;
        accj -= (float)pad * fmaxf(bb2, 0.f);

        g_a[(size_t)u * 32 + j] = accj;
        __syncwarp();   // smf reuse (frag) next node
    }
}

// ---------------- batched epilogue kernel: node-per-thread (round-10) ----
__global__ void __launch_bounds__(512, 1) gru_kernel(
        const float* __restrict__ W1, const float* __restrict__ b1,
        const float* __restrict__ W3, const float* __restrict__ b3,
        const float* __restrict__ Wih, const float* __restrict__ Whh,
        const float* __restrict__ bih, const float* __restrict__ bhh,
        float* __restrict__ out, int write_pq, int n_nodes) {
    __shared__ float sWih[96 * 32];
    __shared__ float sWhh[96 * 32];
    __shared__ float sW3[32 * 32];
    __shared__ float sW1[64 * 32];
    __shared__ float sbih[96], sbhh[96], sb3[32], sb1[32];
    int tid = threadIdx.x;
    for (int i = tid; i < 96 * 32; i += 512) { sWih[i] = Wih[i]; sWhh[i] = Whh[i]; }
    for (int i = tid; i < 32 * 32; i += 512) {
        sW3[i] = W3[i];
        sW1[i] = W1[(i >> 5) * 67 + (i & 31)];
        sW1[1024 + i] = W1[(i >> 5) * 67 + 32 + (i & 31)];
    }
    if (tid < 96) { sbih[tid] = bih[tid]; sbhh[tid] = bhh[tid]; }
    if (tid < 32) { sb3[tid] = b3[tid]; sb1[tid] = b1[tid]; }
    __syncthreads();

    int u = blockIdx.x * 512 + tid;
    if (u >= n_nodes) return;

    float S[32];
    {
        const float4* Sg = (const float4*)&g_a[(size_t)u * 32];
#pragma unroll
        for (int c = 0; c < 8; c++) {
            float4 v = Sg[c];
            S[c * 4] = v.x; S[c * 4 + 1] = v.y; S[c * 4 + 2] = v.z; S[c * 4 + 3] = v.w;
        }
    }
    float deg = (float)(g_off[u + 1] - g_off[u]);

    float a[32];
    for (int o = 0; o < 32; o++) {
        const float4* w = (const float4*)&sW3[o * 32];
        float t0 = 0.f, t1 = 0.f;
#pragma unroll
        for (int c = 0; c < 4; c++) {
            float4 wa = w[2 * c], wb = w[2 * c + 1];
            t0 = fmaf(wa.x, S[8 * c + 0], t0); t0 = fmaf(wa.y, S[8 * c + 1], t0);
            t0 = fmaf(wa.z, S[8 * c + 2], t0); t0 = fmaf(wa.w, S[8 * c + 3], t0);
            t1 = fmaf(wb.x, S[8 * c + 4], t1); t1 = fmaf(wb.y, S[8 * c + 5], t1);
            t1 = fmaf(wb.z, S[8 * c + 6], t1); t1 = fmaf(wb.w, S[8 * c + 7], t1);
        }
        a[o] = t0 + t1 + deg * sb3[o];
    }

    float h[32];
    {
        const float4* Hg = (const float4*)&g_node[(size_t)u * 32];
#pragma unroll
        for (int c = 0; c < 8; c++) {
            float4 v = Hg[c];
            h[c * 4] = v.x; h[c * 4 + 1] = v.y; h[c * 4 + 2] = v.z; h[c * 4 + 3] = v.w;
        }
    }

    float nh[32];
    for (int o = 0; o < 32; o++) {
        const float4* wr = (const float4*)&sWih[o * 32];
        const float4* wz = (const float4*)&sWih[(o + 32) * 32];
        const float4* wn = (const float4*)&sWih[(o + 64) * 32];
        const float4* vr = (const float4*)&sWhh[o * 32];
        const float4* vz = (const float4*)&sWhh[(o + 32) * 32];
        const float4* vn = (const float4*)&sWhh[(o + 64) * 32];
        float gir = sbih[o], giz = sbih[o + 32], gin = sbih[o + 64];
        float ghr = sbhh[o], ghz = sbhh[o + 32], ghn = sbhh[o + 64];
#pragma unroll
        for (int c = 0; c < 8; c++) {
            float a0 = a[4 * c], a1 = a[4 * c + 1], a2 = a[4 * c + 2], a3 = a[4 * c + 3];
            float h0 = h[4 * c], h1 = h[4 * c + 1], h2 = h[4 * c + 2], h3 = h[4 * c + 3];
            float4 w;
            w = wr[c]; gir = fmaf(w.x, a0, gir); gir = fmaf(w.y, a1, gir);
                       gir = fmaf(w.z, a2, gir); gir = fmaf(w.w, a3, gir);
            w = wz[c]; giz = fmaf(w.x, a0, giz); giz = fmaf(w.y, a1, giz);
                       giz = fmaf(w.z, a2, giz); giz = fmaf(w.w, a3, giz);
            w = wn[c]; gin = fmaf(w.x, a0, gin); gin = fmaf(w.y, a1, gin);
                       gin = fmaf(w.z, a2, gin); gin = fmaf(w.w, a3, gin);
            w = vr[c]; ghr = fmaf(w.x, h0, ghr); ghr = fmaf(w.y, h1, ghr);
                       ghr = fmaf(w.z, h2, ghr); ghr = fmaf(w.w, h3, ghr);
            w = vz[c]; ghz = fmaf(w.x, h0, ghz); ghz = fmaf(w.y, h1, ghz);
                       ghz = fmaf(w.z, h2, ghz); ghz = fmaf(w.w, h3, ghz);
            w = vn[c]; ghn = fmaf(w.x, h0, ghn); ghn = fmaf(w.y, h1, ghn);
                       ghn = fmaf(w.z, h2, ghn); ghn = fmaf(w.w, h3, ghn);
        }
        float r = sigf(gir + ghr);
        float z = sigf(giz + ghz);
        float nv = tanhfast(gin + r * ghn);
        nh[o] = (1.f - z) * nv + z * h[o];
    }

    {
        float4* Ng = (float4*)&g_node[(size_t)u * 32];
#pragma unroll
        for (int c = 0; c < 8; c++)
            Ng[c] = make_float4(nh[4 * c], nh[4 * c + 1], nh[4 * c + 2], nh[4 * c + 3]);
        if (out) {
            float4* Og = (float4*)&out[(size_t)u * 32];
#pragma unroll
            for (int c = 0; c < 8; c++)
                Og[c] = make_float4(nh[4 * c], nh[4 * c + 1], nh[4 * c + 2], nh[4 * c + 3]);
        }
    }

    if (write_pq) {
        const float4* Vg = (const float4*)&g_pvc[(size_t)u * 32];
        float4* Pg = (float4*)&g_P[(size_t)u * 32];
        float4* Qg = (float4*)&g_Q[(size_t)u * 32];
        for (int cb = 0; cb < 8; cb++) {
            float4 pv = Vg[cb];
            float pr[4], qr[4];
#pragma unroll
            for (int t = 0; t < 4; t++) {
                int jj = cb * 4 + t;
                const float4* wa = (const float4*)&sW1[jj * 32];
                const float4* wb = (const float4*)&sW1[(jj + 32) * 32];
                float p = 0.f, q = 0.f;
#pragma unroll
                for (int c = 0; c < 8; c++) {
                    float4 w1a = wa[c], w1b = wb[c];
                    p = fmaf(w1a.x, nh[4 * c], p);     p = fmaf(w1a.y, nh[4 * c + 1], p);
                    p = fmaf(w1a.z, nh[4 * c + 2], p); p = fmaf(w1a.w, nh[4 * c + 3], p);
                    q = fmaf(w1b.x, nh[4 * c], q);     q = fmaf(w1b.y, nh[4 * c + 1], q);
                    q = fmaf(w1b.z, nh[4 * c + 2], q); q = fmaf(w1b.w, nh[4 * c + 3], q);
                }
                pr[t] = p + sb1[jj];
                qr[t] = q;
            }
            Pg[cb] = make_float4(pr[0] - pv.x, pr[1] - pv.y, pr[2] - pv.z, pr[3] - pv.w);
            Qg[cb] = make_float4(qr[0] + pv.x, qr[1] + pv.y, qr[2] + pv.z, qr[3] + pv.w);
        }
    }
}

// ---------------- launch ----------------
extern "C" void kernel_launch(void* const* d_in, const int* in_sizes, int n_in,
                              void* d_out, int out_size) {
    const float* pos     = (const float*)d_in[0];
    const float* classes = (const float*)d_in[1];
    const int*   edges   = (const int*)d_in[2];
    int wb = (in_sizes[3] == 1) ? 4 : 3;
    const float* Win = (const float*)d_in[wb + 0];
    const float* bin = (const float*)d_in[wb + 1];
    const float* W1  = (const float*)d_in[wb + 2];
    const float* b1  = (const float*)d_in[wb + 3];
    const float* W2  = (const float*)d_in[wb + 4];
    const float* b2  = (const float*)d_in[wb + 5];
    const float* W3  = (const float*)d_in[wb + 6];
    const float* b3  = (const float*)d_in[wb + 7];
    const float* Wih = (const float*)d_in[wb + 8];
    const float* Whh = (const float*)d_in[wb + 9];
    const float* bih = (const float*)d_in[wb + 10];
    const float* bhh = (const float*)d_in[wb + 11];

    int n_nodes = in_sizes[0] / 3;
    int n_edges = in_sizes[2] / 2;
    int n2e = 2 * n_edges;
    float* out = (float*)d_out;
    int seg = (n_nodes + NB - 1) / NB;

    cudaFuncSetAttribute(edge_kernel,
                         cudaFuncAttributeMaxDynamicSharedMemorySize,
                         EDGE_SMEM_BYTES);

    count_kernel<<<(n2e + 255) / 256, 256>>>(edges, n2e);
    scan1_kernel<<<NB, 256>>>(n_nodes, seg);
    scan23_kernel<<<NB, 256>>>(n_nodes, seg);
    scatter_kernel<<<(n2e + 255) / 256, 256>>>(edges, n_edges);
    embed_pq_kernel<<<(n_nodes + 7) / 8, 256>>>(classes, pos, Win, bin, W1, b1,
                                                n_nodes);

    int gru_grid = (n_nodes + 511) / 512;
    for (int it = 0; it < 6; ++it) {
        edge_kernel<<<296, 256, EDGE_SMEM_BYTES>>>(W2, b2, n_nodes);
        gru_kernel<<<gru_grid, 512>>>(
            W1, b1, W3, b3, Wih, Whh, bih, bhh,
            (it == 5) ? out : (float*)nullptr, (it < 5) ? 1 : 0, n_nodes);
    }
}

// round 13
// speedup vs baseline: 1.1600x; 1.0113x over previous
#include <cuda_runtime.h>
#include <cstdint>

#define NN 50000
#define NE 800000
#define NB 64

// ---------------- scratch (device globals: allocation-free) ----------------
__device__ __align__(16) float g_node[NN * 32];
__device__ __align__(16) float g_P[NN * 32];
__device__ __align__(16) float g_Q[NN * 32];
__device__ __align__(16) float g_pvc[NN * 32];
__device__ __align__(16) float g_a[NN * 32];
__device__ int   g_cnt[NN];     // zero-init at load; re-zeroed by scan23 each run
__device__ int   g_off[NN + 1];
__device__ int   g_cur[NN];
__device__ int   g_csr[2 * NE];
__device__ int   g_bsum[NB];

// ---------------- helpers ----------------
__device__ __forceinline__ uint32_t tf32c(float x) {
    uint32_t r;
    asm("cvt.rna.tf32.f32 %0, %1;" : "=r"(r) : "f"(x));
    return r;
}
__device__ __forceinline__ void mma_tf32(float& d0, float& d1, float& d2, float& d3,
                                         uint32_t a0, uint32_t a1, uint32_t a2, uint32_t a3,
                                         uint32_t b0, uint32_t b1) {
    asm("mma.sync.aligned.m16n8k8.row.col.f32.tf32.tf32.f32 "
        "{%0,%1,%2,%3}, {%4,%5,%6,%7}, {%8,%9}, {%0,%1,%2,%3};"
        : "+f"(d0), "+f"(d1), "+f"(d2), "+f"(d3)
        : "r"(a0), "r"(a1), "r"(a2), "r"(a3), "r"(b0), "r"(b1));
}
__device__ __forceinline__ float sigf(float x) {
    return __fdividef(1.f, 1.f + __expf(-x));
}
__device__ __forceinline__ float tanhfast(float x) {
    float ex = __expf(2.f * x);
    return 1.f - __fdividef(2.f, ex + 1.f);
}
__device__ __forceinline__ void cpasync16(uint32_t dst_s, const void* src) {
    asm volatile("cp.async.cg.shared.global [%0], [%1], 16;"
                 :: "r"(dst_s), "l"(src));
}
__device__ __forceinline__ void cpasync_commit() {
    asm volatile("cp.async.commit_group;" ::: "memory");
}
__device__ __forceinline__ void cpasync_wait0() {
    asm volatile("cp.async.wait_group 0;" ::: "memory");
}
__device__ __forceinline__ void cpasync_wait1() {
    asm volatile("cp.async.wait_group 1;" ::: "memory");
}

// fragment store of one relu'd float4 (verified layout, rounds 8-12)
__device__ __forceinline__ void frag_store(uint32_t* fragT, int row16, int jc,
                                           float4 pq4, float4 q, bool valid) {
    float h0 = fmaxf(pq4.x + q.x, 0.f);
    float h1 = fmaxf(pq4.y + q.y, 0.f);
    float h2 = fmaxf(pq4.z + q.z, 0.f);
    float h3 = fmaxf(pq4.w + q.w, 0.f);
    if (!valid) { h0 = h1 = h2 = h3 = 0.f; }
    int T0 = ((row16 >> 3) & 1) + (jc << 1);
    int bA = T0 * 32;
    int sw = (row16 & 7) + 2 * T0;
    fragT[bA + ((sw     ) & 31)] = tf32c(h0);
    fragT[bA + ((sw +  8) & 31)] = tf32c(h1);
    fragT[bA + ((sw + 16) & 31)] = tf32c(h2);
    fragT[bA + ((sw + 24) & 31)] = tf32c(h3);
}

// one m16n8k8-tile pass2 (4 n-tiles x 4 k-steps), accumulate relu into acc[8]
__device__ __forceinline__ void pass2_tile(const uint32_t* fragT, int permj,
                                           const uint32_t* B0, const uint32_t* B1,
                                           const float* b2e, const float* b2o,
                                           float* acc) {
    uint32_t a[16];
#pragma unroll
    for (int idx = 0; idx < 16; idx++)
        a[idx] = fragT[idx * 32 + ((permj + 2 * idx) & 31)];
#pragma unroll
    for (int nt = 0; nt < 4; nt++) {
        float d0 = 0.f, d1 = 0.f, d2 = 0.f, d3 = 0.f;
#pragma unroll
        for (int kt = 0; kt < 4; kt++)
            mma_tf32(d0, d1, d2, d3,
                     a[kt * 4 + 0], a[kt * 4 + 1], a[kt * 4 + 2], a[kt * 4 + 3],
                     B0[kt * 4 + nt], B1[kt * 4 + nt]);
        acc[nt * 2 + 0] += fmaxf(d0 + b2e[nt], 0.f) + fmaxf(d2 + b2e[nt], 0.f);
        acc[nt * 2 + 1] += fmaxf(d1 + b2o[nt], 0.f) + fmaxf(d3 + b2o[nt], 0.f);
    }
}

// ---------------- prep kernels ----------------
__global__ void count_kernel(const int* __restrict__ e, int n2e) {
    int i = blockIdx.x * blockDim.x + threadIdx.x;
    if (i < n2e) atomicAdd(&g_cnt[e[i]], 1);
}

__global__ void scan1_kernel(int n, int seg) {
    int b = blockIdx.x;
    int beg = b * seg, end = min(beg + seg, n);
    int tid = threadIdx.x;
    int s = 0;
    for (int i = beg + tid; i < end; i += 256) s += g_cnt[i];
    __shared__ int sm[8];
    int lane = tid & 31, w = tid >> 5;
#pragma unroll
    for (int o = 16; o >= 1; o >>= 1) s += __shfl_down_sync(0xffffffffu, s, o);
    if (lane == 0) sm[w] = s;
    __syncthreads();
    if (tid == 0) {
        int t = 0;
#pragma unroll
        for (int k = 0; k < 8; k++) t += sm[k];
        g_bsum[b] = t;
    }
}

__global__ void scan23_kernel(int n, int seg) {
    int b = blockIdx.x, tid = threadIdx.x;
    __shared__ int s_pre;
    if (tid == 0) {
        int t = 0;
        for (int k = 0; k < b; k++) t += g_bsum[k];
        s_pre = t;
    }
    __syncthreads();
    int beg = b * seg, end = min(beg + seg, n);
    int len = max(end - beg, 0);
    int c = (len + 255) / 256;
    int tb = min(beg + tid * c, end), te = min(tb + c, end);
    int s = 0;
    for (int i = tb; i < te; i++) s += g_cnt[i];
    int lane = tid & 31, w = tid >> 5;
    int v = s;
#pragma unroll
    for (int o = 1; o < 32; o <<= 1) {
        int t = __shfl_up_sync(0xffffffffu, v, o);
        if (lane >= o) v += t;
    }
    __shared__ int wt[8], wpre[8];
    if (lane == 31) wt[w] = v;
    __syncthreads();
    if (tid < 8) {
        int x = wt[tid];
#pragma unroll
        for (int o = 1; o < 8; o <<= 1) {
            int t = __shfl_up_sync(0xffu, x, o);
            if (tid >= o) x += t;
        }
        wpre[tid] = x;
    }
    __syncthreads();
    int excl = (v - s) + (w > 0 ? wpre[w - 1] : 0);
    int run = s_pre + excl;
    for (int i = tb; i < te; i++) {
        g_off[i] = run;
        g_cur[i] = run;
        run += g_cnt[i];
    }
    for (int i = tb; i < te; i++) g_cnt[i] = 0;
    if (b == gridDim.x - 1 && tid == 255) g_off[n] = run;
}

__global__ void scatter_kernel(const int* __restrict__ e, int nE) {
    int i = blockIdx.x * blockDim.x + threadIdx.x;
    if (i >= 2 * nE) return;
    int src = e[i];
    int dst = (i < nE) ? e[i + nE] : e[i - nE];
    int slot = atomicAdd(&g_cur[src], 1);
    g_csr[slot] = dst;
}

// once: node0 = classes@Win.T + bin ; pvc = pos@W1c.T ; P,Q from node0
__global__ void embed_pq_kernel(const float* __restrict__ classes,
                                const float* __restrict__ pos,
                                const float* __restrict__ Win,
                                const float* __restrict__ bin,
                                const float* __restrict__ W1,
                                const float* __restrict__ b1,
                                int n_nodes) {
    int warp = (blockIdx.x * blockDim.x + threadIdx.x) >> 5;
    int j = threadIdx.x & 31;
    if (warp >= n_nodes) return;
    int u = warp;

    float w[16];
#pragma unroll
    for (int k = 0; k < 16; k++) w[k] = Win[j * 16 + k];
    float c = (j < 16) ? classes[u * 16 + j] : 0.f;
    float acc = bin[j];
#pragma unroll
    for (int k = 0; k < 16; k++)
        acc = fmaf(w[k], __shfl_sync(0xffffffffu, c, k), acc);
    g_node[u * 32 + j] = acc;

    float p0 = pos[u * 3 + 0], p1 = pos[u * 3 + 1], p2 = pos[u * 3 + 2];
    float pv = p0 * W1[j * 67 + 64] + p1 * W1[j * 67 + 65] + p2 * W1[j * 67 + 66];
    g_pvc[u * 32 + j] = pv;

    float p = 0.f, q = 0.f;
#pragma unroll
    for (int k = 0; k < 32; k++) {
        float val = __shfl_sync(0xffffffffu, acc, k);
        p = fmaf(W1[j * 67 + k], val, p);
        q = fmaf(W1[j * 67 + 32 + k], val, q);
    }
    g_P[u * 32 + j] = p + b1[j] - pv;
    g_Q[u * 32 + j] = q + pv;
}

// ---------------- message-pass kernel: node-pipelined cp.async staging ----
// While computing node u: stage node u+1's chunk-0 (cp.async) and prefetch
// node u+2's offsets + P row. One commit group per node -> wait_group 1 at
// each node's top. Chunks >=1 use the direct-LDG path.
#define EDGE_SMEM_BYTES (24576 * 4)

__global__ void __launch_bounds__(256, 2) edge_kernel(
        const float* __restrict__ W2, const float* __restrict__ b2,
        int n_nodes) {
    extern __shared__ float sm[];
    int tid = threadIdx.x, wl = tid >> 5, j = tid & 31;

    uint32_t B0[16], B1[16];
#pragma unroll
    for (int kt = 0; kt < 4; kt++)
#pragma unroll
        for (int nt = 0; nt < 4; nt++) {
            int ncol = nt * 8 + (j >> 2);
            int krow = kt * 8 + (j & 3);
            B0[kt * 4 + nt] = tf32c(W2[ncol * 32 + krow]);
            B1[kt * 4 + nt] = tf32c(W2[ncol * 32 + krow + 4]);
        }
    float b2e[4], b2o[4];
#pragma unroll
    for (int nt = 0; nt < 4; nt++) {
        b2e[nt] = b2[nt * 8 + (j & 3) * 2];
        b2o[nt] = b2[nt * 8 + (j & 3) * 2 + 1];
    }
    float bb2 = b2[j];

    float* frag  = sm + wl * 1024;          // tile A at +0, tile B at +512
    float* stage = sm + 8192 + wl * 2048;   // buf b at + b*1024
    uint32_t* fragA = (uint32_t*)frag;
    uint32_t* fragB = (uint32_t*)(frag + 512);
    float* smf = frag;

    int jc = j & 7;            // col group 0..7 (16B units)
    int jr = j >> 3;           // row residue 0..3
    int permj = (j >> 2) + (j & 3) * 8;
    int nw = gridDim.x * 8;

    int u = blockIdx.x * 8 + wl;
    int s = 0, e = 0;
    float pj = 0.f;
    int s2 = 0, e2 = 0;
    float pj2 = 0.f;

    // prologue: stage node u's chunk0 into buf0; prefetch u2's offsets+P
    if (u < n_nodes) {
        s = g_off[u]; e = g_off[u + 1];
        pj = g_P[(size_t)u * 32 + j];
        int vc = (s + j < e) ? g_csr[s + j] : 0;
        int cnt0 = min(32, e - s);
#pragma unroll
        for (int k = 0; k < 8; k++) {
            int row = jr + 4 * k;
            int vv = __shfl_sync(0xffffffffu, vc, row);
            if (row < cnt0) {
                uint32_t d = (uint32_t)__cvta_generic_to_shared(
                    stage + row * 32 + ((jc ^ (row & 7)) << 2));
                cpasync16(d, &g_Q[(size_t)vv * 32 + jc * 4]);
            }
        }
        cpasync_commit();
        int u2 = u + nw;
        if (u2 < n_nodes) {
            s2 = g_off[u2]; e2 = g_off[u2 + 1];
            pj2 = g_P[(size_t)u2 * 32 + j];
        }
    }

    int ib = 0;
    for (; u < n_nodes; u += nw, ib ^= 1) {
        int u2 = u + nw;
        // stage u2's chunk0 into the other buffer (csr load uses prefetched s2/e2)
        if (u2 < n_nodes) {
            int vc2 = (s2 + j < e2) ? g_csr[s2 + j] : 0;
            float* stg1 = stage + (ib ^ 1) * 1024;
            int cnt0 = min(32, e2 - s2);
#pragma unroll
            for (int k = 0; k < 8; k++) {
                int row = jr + 4 * k;
                int vv = __shfl_sync(0xffffffffu, vc2, row);
                if (row < cnt0) {
                    uint32_t d = (uint32_t)__cvta_generic_to_shared(
                        stg1 + row * 32 + ((jc ^ (row & 7)) << 2));
                    cpasync16(d, &g_Q[(size_t)vv * 32 + jc * 4]);
                }
            }
            cpasync_commit();
        }
        // prefetch u3's offsets + P row (consumed next iteration)
        int u3 = u + 2 * nw;
        int s3 = 0, e3 = 0;
        float pj3 = 0.f;
        if (u3 < n_nodes) {
            s3 = g_off[u3]; e3 = g_off[u3 + 1];
            pj3 = g_P[(size_t)u3 * 32 + j];
        }
        // wait for OUR node's staging (landed during previous node's compute)
        if (u2 < n_nodes) cpasync_wait1(); else cpasync_wait0();
        __syncwarp();

        float4 pq4;
        pq4.x = __shfl_sync(0xffffffffu, pj, jc * 4 + 0);
        pq4.y = __shfl_sync(0xffffffffu, pj, jc * 4 + 1);
        pq4.z = __shfl_sync(0xffffffffu, pj, jc * 4 + 2);
        pq4.w = __shfl_sync(0xffffffffu, pj, jc * 4 + 3);

        float acc[8];
#pragma unroll
        for (int r = 0; r < 8; r++) acc[r] = 0.f;

        int deg = e - s;
        float* stg = stage + ib * 1024;
        // issue chunk1's csr early (hides latency under chunk0 compute)
        int vd = (s + 32 + j < e) ? g_csr[s + 32 + j] : 0;

        if (deg > 0) {
            int cnt = min(32, deg);
            bool hasB = cnt > 16;
            // pass1 from staged buffer
#pragma unroll
            for (int k = 0; k < 4; k++) {
                int row16 = jr + 4 * k;
                float4 q = *(const float4*)&stg[row16 * 32 + ((jc ^ (row16 & 7)) << 2)];
                frag_store(fragA, row16, jc, pq4, q, row16 < cnt);
            }
            if (hasB) {
#pragma unroll
                for (int k = 0; k < 4; k++) {
                    int row16 = jr + 4 * k;
                    int prow = 16 + row16;
                    float4 q = *(const float4*)&stg[prow * 32 + ((jc ^ (prow & 7)) << 2)];
                    frag_store(fragB, row16, jc, pq4, q, prow < cnt);
                }
            }
            __syncwarp();
            pass2_tile(fragA, permj, B0, B1, b2e, b2o, acc);
            if (hasB) pass2_tile(fragB, permj, B0, B1, b2e, b2o, acc);

            // remaining chunks: direct-LDG path
            for (int base = s + 32; base < e; base += 32) {
                int cnt2 = min(32, e - base);
                int vdn = (base + 32 + j < e) ? g_csr[base + 32 + j] : 0;
                bool hB2 = cnt2 > 16;
                __syncwarp();
#pragma unroll
                for (int k = 0; k < 4; k++) {
                    int row = jr + 4 * k;
                    int vv = __shfl_sync(0xffffffffu, vd, row);
                    float4 q = *(const float4*)&g_Q[(size_t)vv * 32 + jc * 4];
                    frag_store(fragA, row, jc, pq4, q, row < cnt2);
                }
                if (hB2) {
#pragma unroll
                    for (int k = 4; k < 8; k++) {
                        int row = jr + 4 * k;
                        int vv = __shfl_sync(0xffffffffu, vd, row);
                        float4 q = *(const float4*)&g_Q[(size_t)vv * 32 + jc * 4];
                        frag_store(fragB, row - 16, jc, pq4, q, row < cnt2);
                    }
                }
                __syncwarp();
                pass2_tile(fragA, permj, B0, B1, b2e, b2o, acc);
                if (hB2) pass2_tile(fragB, permj, B0, B1, b2e, b2o, acc);
                vd = vdn;
            }
        }

        // cross-lane reduce + remap to col-per-lane (layout verified round 8)
#pragma unroll
        for (int o = 4; o < 32; o <<= 1)
#pragma unroll
            for (int r = 0; r < 8; r++)
                acc[r] += __shfl_xor_sync(0xffffffffu, acc[r], o);
        __syncwarp();
#pragma unroll
        for (int r = 0; r < 8; r++) smf[r * 32 + j] = acc[r];
        __syncwarp();
        float accj = smf[(((j >> 3) << 1) + (j & 1)) * 32 + ((j & 7) >> 1)];

        int pad = ((deg + 15) & ~15) - deg;
        accj -= (float)pad * fmaxf(bb2, 0.f);

        g_a[(size_t)u * 32 + j] = accj;
        __syncwarp();   // frag/smf reuse + stage WAR fence before next iteration

        // rotate pipeline state
        s = s2; e = e2; pj = pj2;
        s2 = s3; e2 = e3; pj2 = pj3;
    }
}

// ---------------- batched epilogue kernel: node-per-thread (round-10) ----
__global__ void __launch_bounds__(512, 1) gru_kernel(
        const float* __restrict__ W1, const float* __restrict__ b1,
        const float* __restrict__ W3, const float* __restrict__ b3,
        const float* __restrict__ Wih, const float* __restrict__ Whh,
        const float* __restrict__ bih, const float* __restrict__ bhh,
        float* __restrict__ out, int write_pq, int n_nodes) {
    __shared__ float sWih[96 * 32];
    __shared__ float sWhh[96 * 32];
    __shared__ float sW3[32 * 32];
    __shared__ float sW1[64 * 32];
    __shared__ float sbih[96], sbhh[96], sb3[32], sb1[32];
    int tid = threadIdx.x;
    for (int i = tid; i < 96 * 32; i += 512) { sWih[i] = Wih[i]; sWhh[i] = Whh[i]; }
    for (int i = tid; i < 32 * 32; i += 512) {
        sW3[i] = W3[i];
        sW1[i] = W1[(i >> 5) * 67 + (i & 31)];
        sW1[1024 + i] = W1[(i >> 5) * 67 + 32 + (i & 31)];
    }
    if (tid < 96) { sbih[tid] = bih[tid]; sbhh[tid] = bhh[tid]; }
    if (tid < 32) { sb3[tid] = b3[tid]; sb1[tid] = b1[tid]; }
    __syncthreads();

    int u = blockIdx.x * 512 + tid;
    if (u >= n_nodes) return;

    float S[32];
    {
        const float4* Sg = (const float4*)&g_a[(size_t)u * 32];
#pragma unroll
        for (int c = 0; c < 8; c++) {
            float4 v = Sg[c];
            S[c * 4] = v.x; S[c * 4 + 1] = v.y; S[c * 4 + 2] = v.z; S[c * 4 + 3] = v.w;
        }
    }
    float deg = (float)(g_off[u + 1] - g_off[u]);

    float a[32];
    for (int o = 0; o < 32; o++) {
        const float4* w = (const float4*)&sW3[o * 32];
        float t0 = 0.f, t1 = 0.f;
#pragma unroll
        for (int c = 0; c < 4; c++) {
            float4 wa = w[2 * c], wb = w[2 * c + 1];
            t0 = fmaf(wa.x, S[8 * c + 0], t0); t0 = fmaf(wa.y, S[8 * c + 1], t0);
            t0 = fmaf(wa.z, S[8 * c + 2], t0); t0 = fmaf(wa.w, S[8 * c + 3], t0);
            t1 = fmaf(wb.x, S[8 * c + 4], t1); t1 = fmaf(wb.y, S[8 * c + 5], t1);
            t1 = fmaf(wb.z, S[8 * c + 6], t1); t1 = fmaf(wb.w, S[8 * c + 7], t1);
        }
        a[o] = t0 + t1 + deg * sb3[o];
    }

    float h[32];
    {
        const float4* Hg = (const float4*)&g_node[(size_t)u * 32];
#pragma unroll
        for (int c = 0; c < 8; c++) {
            float4 v = Hg[c];
            h[c * 4] = v.x; h[c * 4 + 1] = v.y; h[c * 4 + 2] = v.z; h[c * 4 + 3] = v.w;
        }
    }

    float nh[32];
    for (int o = 0; o < 32; o++) {
        const float4* wr = (const float4*)&sWih[o * 32];
        const float4* wz = (const float4*)&sWih[(o + 32) * 32];
        const float4* wn = (const float4*)&sWih[(o + 64) * 32];
        const float4* vr = (const float4*)&sWhh[o * 32];
        const float4* vz = (const float4*)&sWhh[(o + 32) * 32];
        const float4* vn = (const float4*)&sWhh[(o + 64) * 32];
        float gir = sbih[o], giz = sbih[o + 32], gin = sbih[o + 64];
        float ghr = sbhh[o], ghz = sbhh[o + 32], ghn = sbhh[o + 64];
#pragma unroll
        for (int c = 0; c < 8; c++) {
            float a0 = a[4 * c], a1 = a[4 * c + 1], a2 = a[4 * c + 2], a3 = a[4 * c + 3];
            float h0 = h[4 * c], h1 = h[4 * c + 1], h2 = h[4 * c + 2], h3 = h[4 * c + 3];
            float4 w;
            w = wr[c]; gir = fmaf(w.x, a0, gir); gir = fmaf(w.y, a1, gir);
                       gir = fmaf(w.z, a2, gir); gir = fmaf(w.w, a3, gir);
            w = wz[c]; giz = fmaf(w.x, a0, giz); giz = fmaf(w.y, a1, giz);
                       giz = fmaf(w.z, a2, giz); giz = fmaf(w.w, a3, giz);
            w = wn[c]; gin = fmaf(w.x, a0, gin); gin = fmaf(w.y, a1, gin);
                       gin = fmaf(w.z, a2, gin); gin = fmaf(w.w, a3, gin);
            w = vr[c]; ghr = fmaf(w.x, h0, ghr); ghr = fmaf(w.y, h1, ghr);
                       ghr = fmaf(w.z, h2, ghr); ghr = fmaf(w.w, h3, ghr);
            w = vz[c]; ghz = fmaf(w.x, h0, ghz); ghz = fmaf(w.y, h1, ghz);
                       ghz = fmaf(w.z, h2, ghz); ghz = fmaf(w.w, h3, ghz);
            w = vn[c]; ghn = fmaf(w.x, h0, ghn); ghn = fmaf(w.y, h1, ghn);
                       ghn = fmaf(w.z, h2, ghn); ghn = fmaf(w.w, h3, ghn);
        }
        float r = sigf(gir + ghr);
        float z = sigf(giz + ghz);
        float nv = tanhfast(gin + r * ghn);
        nh[o] = (1.f - z) * nv + z * h[o];
    }

    {
        float4* Ng = (float4*)&g_node[(size_t)u * 32];
#pragma unroll
        for (int c = 0; c < 8; c++)
            Ng[c] = make_float4(nh[4 * c], nh[4 * c + 1], nh[4 * c + 2], nh[4 * c + 3]);
        if (out) {
            float4* Og = (float4*)&out[(size_t)u * 32];
#pragma unroll
            for (int c = 0; c < 8; c++)
                Og[c] = make_float4(nh[4 * c], nh[4 * c + 1], nh[4 * c + 2], nh[4 * c + 3]);
        }
    }

    if (write_pq) {
        const float4* Vg = (const float4*)&g_pvc[(size_t)u * 32];
        float4* Pg = (float4*)&g_P[(size_t)u * 32];
        float4* Qg = (float4*)&g_Q[(size_t)u * 32];
        for (int cb = 0; cb < 8; cb++) {
            float4 pv = Vg[cb];
            float pr[4], qr[4];
#pragma unroll
            for (int t = 0; t < 4; t++) {
                int jj = cb * 4 + t;
                const float4* wa = (const float4*)&sW1[jj * 32];
                const float4* wb = (const float4*)&sW1[(jj + 32) * 32];
                float p = 0.f, q = 0.f;
#pragma unroll
                for (int c = 0; c < 8; c++) {
                    float4 w1a = wa[c], w1b = wb[c];
                    p = fmaf(w1a.x, nh[4 * c], p);     p = fmaf(w1a.y, nh[4 * c + 1], p);
                    p = fmaf(w1a.z, nh[4 * c + 2], p); p = fmaf(w1a.w, nh[4 * c + 3], p);
                    q = fmaf(w1b.x, nh[4 * c], q);     q = fmaf(w1b.y, nh[4 * c + 1], q);
                    q = fmaf(w1b.z, nh[4 * c + 2], q); q = fmaf(w1b.w, nh[4 * c + 3], q);
                }
                pr[t] = p + sb1[jj];
                qr[t] = q;
            }
            Pg[cb] = make_float4(pr[0] - pv.x, pr[1] - pv.y, pr[2] - pv.z, pr[3] - pv.w);
            Qg[cb] = make_float4(qr[0] + pv.x, qr[1] + pv.y, qr[2] + pv.z, qr[3] + pv.w);
        }
    }
}

// ---------------- launch ----------------
extern "C" void kernel_launch(void* const* d_in, const int* in_sizes, int n_in,
                              void* d_out, int out_size) {
    const float* pos     = (const float*)d_in[0];
    const float* classes = (const float*)d_in[1];
    const int*   edges   = (const int*)d_in[2];
    int wb = (in_sizes[3] == 1) ? 4 : 3;
    const float* Win = (const float*)d_in[wb + 0];
    const float* bin = (const float*)d_in[wb + 1];
    const float* W1  = (const float*)d_in[wb + 2];
    const float* b1  = (const float*)d_in[wb + 3];
    const float* W2  = (const float*)d_in[wb + 4];
    const float* b2  = (const float*)d_in[wb + 5];
    const float* W3  = (const float*)d_in[wb + 6];
    const float* b3  = (const float*)d_in[wb + 7];
    const float* Wih = (const float*)d_in[wb + 8];
    const float* Whh = (const float*)d_in[wb + 9];
    const float* bih = (const float*)d_in[wb + 10];
    const float* bhh = (const float*)d_in[wb + 11];

    int n_nodes = in_sizes[0] / 3;
    int n_edges = in_sizes[2] / 2;
    int n2e = 2 * n_edges;
    float* out = (float*)d_out;
    int seg = (n_nodes + NB - 1) / NB;

    cudaFuncSetAttribute(edge_kernel,
                         cudaFuncAttributeMaxDynamicSharedMemorySize,
                         EDGE_SMEM_BYTES);

    count_kernel<<<(n2e + 255) / 256, 256>>>(edges, n2e);
    scan1_kernel<<<NB, 256>>>(n_nodes, seg);
    scan23_kernel<<<NB, 256>>>(n_nodes, seg);
    scatter_kernel<<<(n2e + 255) / 256, 256>>>(edges, n_edges);
    embed_pq_kernel<<<(n_nodes + 7) / 8, 256>>>(classes, pos, Win, bin, W1, b1,
                                                n_nodes);

    int gru_grid = (n_nodes + 511) / 512;
    for (int it = 0; it < 6; ++it) {
        edge_kernel<<<296, 256, EDGE_SMEM_BYTES>>>(W2, b2, n_nodes);
        gru_kernel<<<gru_grid, 512>>>(
            W1, b1, W3, b3, Wih, Whh, bih, bhh,
            (it == 5) ? out : (float*)nullptr, (it < 5) ? 1 : 0, n_nodes);
    }
}

// round 14
// speedup vs baseline: 1.3082x; 1.1278x over previous
#include <cuda_runtime.h>
#include <cstdint>

#define NN 50000
#define NE 800000
#define NB 64

// ---------------- scratch (device globals: allocation-free) ----------------
__device__ __align__(16) float g_node[NN * 32];
__device__ __align__(16) float g_P[NN * 32];
__device__ __align__(16) float g_Q[NN * 32];
__device__ __align__(16) float g_pvc[NN * 32];
__device__ __align__(16) float g_a[NN * 32];
__device__ __align__(16) float g_Wf[96 * 32];   // Wih @ W3 (fused)
__device__ float g_bf[96];                       // Wih @ b3
__device__ int   g_cnt[NN];     // zero-init at load; re-zeroed by scan23 each run
__device__ int   g_off[NN + 1];
__device__ int   g_cur[NN];
__device__ int   g_csr[2 * NE];
__device__ int   g_bsum[NB];

// ---------------- helpers ----------------
__device__ __forceinline__ uint32_t tf32c(float x) {
    uint32_t r;
    asm("cvt.rna.tf32.f32 %0, %1;" : "=r"(r) : "f"(x));
    return r;
}
__device__ __forceinline__ void mma_tf32(float& d0, float& d1, float& d2, float& d3,
                                         uint32_t a0, uint32_t a1, uint32_t a2, uint32_t a3,
                                         uint32_t b0, uint32_t b1) {
    asm("mma.sync.aligned.m16n8k8.row.col.f32.tf32.tf32.f32 "
        "{%0,%1,%2,%3}, {%4,%5,%6,%7}, {%8,%9}, {%0,%1,%2,%3};"
        : "+f"(d0), "+f"(d1), "+f"(d2), "+f"(d3)
        : "r"(a0), "r"(a1), "r"(a2), "r"(a3), "r"(b0), "r"(b1));
}
__device__ __forceinline__ float sigf(float x) {
    return __fdividef(1.f, 1.f + __expf(-x));
}
__device__ __forceinline__ float tanhfast(float x) {
    float ex = __expf(2.f * x);
    return 1.f - __fdividef(2.f, ex + 1.f);
}
__device__ __forceinline__ void cpasync16(uint32_t dst_s, const void* src) {
    asm volatile("cp.async.cg.shared.global [%0], [%1], 16;"
                 :: "r"(dst_s), "l"(src));
}
__device__ __forceinline__ void cpasync_commit() {
    asm volatile("cp.async.commit_group;" ::: "memory");
}
__device__ __forceinline__ void cpasync_wait0() {
    asm volatile("cp.async.wait_group 0;" ::: "memory");
}
__device__ __forceinline__ void cpasync_wait1() {
    asm volatile("cp.async.wait_group 1;" ::: "memory");
}

// fragment store of one relu'd float4 (verified layout, rounds 8-13)
__device__ __forceinline__ void frag_store(uint32_t* fragT, int row16, int jc,
                                           float4 pq4, float4 q, bool valid) {
    float h0 = fmaxf(pq4.x + q.x, 0.f);
    float h1 = fmaxf(pq4.y + q.y, 0.f);
    float h2 = fmaxf(pq4.z + q.z, 0.f);
    float h3 = fmaxf(pq4.w + q.w, 0.f);
    if (!valid) { h0 = h1 = h2 = h3 = 0.f; }
    int T0 = ((row16 >> 3) & 1) + (jc << 1);
    int bA = T0 * 32;
    int sw = (row16 & 7) + 2 * T0;
    fragT[bA + ((sw     ) & 31)] = tf32c(h0);
    fragT[bA + ((sw +  8) & 31)] = tf32c(h1);
    fragT[bA + ((sw + 16) & 31)] = tf32c(h2);
    fragT[bA + ((sw + 24) & 31)] = tf32c(h3);
}

__device__ __forceinline__ void pass2_tile(const uint32_t* fragT, int permj,
                                           const uint32_t* B0, const uint32_t* B1,
                                           const float* b2e, const float* b2o,
                                           float* acc) {
    uint32_t a[16];
#pragma unroll
    for (int idx = 0; idx < 16; idx++)
        a[idx] = fragT[idx * 32 + ((permj + 2 * idx) & 31)];
#pragma unroll
    for (int nt = 0; nt < 4; nt++) {
        float d0 = 0.f, d1 = 0.f, d2 = 0.f, d3 = 0.f;
#pragma unroll
        for (int kt = 0; kt < 4; kt++)
            mma_tf32(d0, d1, d2, d3,
                     a[kt * 4 + 0], a[kt * 4 + 1], a[kt * 4 + 2], a[kt * 4 + 3],
                     B0[kt * 4 + nt], B1[kt * 4 + nt]);
        acc[nt * 2 + 0] += fmaxf(d0 + b2e[nt], 0.f) + fmaxf(d2 + b2e[nt], 0.f);
        acc[nt * 2 + 1] += fmaxf(d1 + b2o[nt], 0.f) + fmaxf(d3 + b2o[nt], 0.f);
    }
}

// ---------------- prep kernels ----------------
__global__ void count_kernel(const int* __restrict__ e, int n2e) {
    int i = blockIdx.x * blockDim.x + threadIdx.x;
    if (i < n2e) atomicAdd(&g_cnt[e[i]], 1);
}

__global__ void scan1_kernel(int n, int seg) {
    int b = blockIdx.x;
    int beg = b * seg, end = min(beg + seg, n);
    int tid = threadIdx.x;
    int s = 0;
    for (int i = beg + tid; i < end; i += 256) s += g_cnt[i];
    __shared__ int sm[8];
    int lane = tid & 31, w = tid >> 5;
#pragma unroll
    for (int o = 16; o >= 1; o >>= 1) s += __shfl_down_sync(0xffffffffu, s, o);
    if (lane == 0) sm[w] = s;
    __syncthreads();
    if (tid == 0) {
        int t = 0;
#pragma unroll
        for (int k = 0; k < 8; k++) t += sm[k];
        g_bsum[b] = t;
    }
}

__global__ void scan23_kernel(int n, int seg) {
    int b = blockIdx.x, tid = threadIdx.x;
    __shared__ int s_pre;
    if (tid == 0) {
        int t = 0;
        for (int k = 0; k < b; k++) t += g_bsum[k];
        s_pre = t;
    }
    __syncthreads();
    int beg = b * seg, end = min(beg + seg, n);
    int len = max(end - beg, 0);
    int c = (len + 255) / 256;
    int tb = min(beg + tid * c, end), te = min(tb + c, end);
    int s = 0;
    for (int i = tb; i < te; i++) s += g_cnt[i];
    int lane = tid & 31, w = tid >> 5;
    int v = s;
#pragma unroll
    for (int o = 1; o < 32; o <<= 1) {
        int t = __shfl_up_sync(0xffffffffu, v, o);
        if (lane >= o) v += t;
    }
    __shared__ int wt[8], wpre[8];
    if (lane == 31) wt[w] = v;
    __syncthreads();
    if (tid < 8) {
        int x = wt[tid];
#pragma unroll
        for (int o = 1; o < 8; o <<= 1) {
            int t = __shfl_up_sync(0xffu, x, o);
            if (tid >= o) x += t;
        }
        wpre[tid] = x;
    }
    __syncthreads();
    int excl = (v - s) + (w > 0 ? wpre[w - 1] : 0);
    int run = s_pre + excl;
    for (int i = tb; i < te; i++) {
        g_off[i] = run;
        g_cur[i] = run;
        run += g_cnt[i];
    }
    for (int i = tb; i < te; i++) g_cnt[i] = 0;
    if (b == gridDim.x - 1 && tid == 255) g_off[n] = run;
}

__global__ void scatter_kernel(const int* __restrict__ e, int nE) {
    int i = blockIdx.x * blockDim.x + threadIdx.x;
    if (i >= 2 * nE) return;
    int src = e[i];
    int dst = (i < nE) ? e[i + nE] : e[i - nE];
    int slot = atomicAdd(&g_cur[src], 1);
    g_csr[slot] = dst;
}

// precompute fused GRU input weights: Wf = Wih @ W3, bf = Wih @ b3
__global__ void wf_kernel(const float* __restrict__ Wih,
                          const float* __restrict__ W3,
                          const float* __restrict__ b3) {
    int idx = blockIdx.x * 256 + threadIdx.x;
    if (idx < 96 * 32) {
        int g = idx >> 5, k = idx & 31;
        float s = 0.f;
#pragma unroll
        for (int o = 0; o < 32; o++)
            s = fmaf(Wih[g * 32 + o], W3[o * 32 + k], s);
        g_Wf[idx] = s;
    }
    if (idx < 96) {
        float s = 0.f;
#pragma unroll
        for (int o = 0; o < 32; o++)
            s = fmaf(Wih[idx * 32 + o], b3[o], s);
        g_bf[idx] = s;
    }
}

// once: node0 = classes@Win.T + bin ; pvc = pos@W1c.T ; P,Q from node0
__global__ void embed_pq_kernel(const float* __restrict__ classes,
                                const float* __restrict__ pos,
                                const float* __restrict__ Win,
                                const float* __restrict__ bin,
                                const float* __restrict__ W1,
                                const float* __restrict__ b1,
                                int n_nodes) {
    int warp = (blockIdx.x * blockDim.x + threadIdx.x) >> 5;
    int j = threadIdx.x & 31;
    if (warp >= n_nodes) return;
    int u = warp;

    float w[16];
#pragma unroll
    for (int k = 0; k < 16; k++) w[k] = Win[j * 16 + k];
    float c = (j < 16) ? classes[u * 16 + j] : 0.f;
    float acc = bin[j];
#pragma unroll
    for (int k = 0; k < 16; k++)
        acc = fmaf(w[k], __shfl_sync(0xffffffffu, c, k), acc);
    g_node[u * 32 + j] = acc;

    float p0 = pos[u * 3 + 0], p1 = pos[u * 3 + 1], p2 = pos[u * 3 + 2];
    float pv = p0 * W1[j * 67 + 64] + p1 * W1[j * 67 + 65] + p2 * W1[j * 67 + 66];
    g_pvc[u * 32 + j] = pv;

    float p = 0.f, q = 0.f;
#pragma unroll
    for (int k = 0; k < 32; k++) {
        float val = __shfl_sync(0xffffffffu, acc, k);
        p = fmaf(W1[j * 67 + k], val, p);
        q = fmaf(W1[j * 67 + 32 + k], val, q);
    }
    g_P[u * 32 + j] = p + b1[j] - pv;
    g_Q[u * 32 + j] = q + pv;
}

// ---------------- message-pass kernel (unchanged from round 13) ----------
#define EDGE_SMEM_BYTES (24576 * 4)

__global__ void __launch_bounds__(256, 2) edge_kernel(
        const float* __restrict__ W2, const float* __restrict__ b2,
        int n_nodes) {
    extern __shared__ float sm[];
    int tid = threadIdx.x, wl = tid >> 5, j = tid & 31;

    uint32_t B0[16], B1[16];
#pragma unroll
    for (int kt = 0; kt < 4; kt++)
#pragma unroll
        for (int nt = 0; nt < 4; nt++) {
            int ncol = nt * 8 + (j >> 2);
            int krow = kt * 8 + (j & 3);
            B0[kt * 4 + nt] = tf32c(W2[ncol * 32 + krow]);
            B1[kt * 4 + nt] = tf32c(W2[ncol * 32 + krow + 4]);
        }
    float b2e[4], b2o[4];
#pragma unroll
    for (int nt = 0; nt < 4; nt++) {
        b2e[nt] = b2[nt * 8 + (j & 3) * 2];
        b2o[nt] = b2[nt * 8 + (j & 3) * 2 + 1];
    }
    float bb2 = b2[j];

    float* frag  = sm + wl * 1024;
    float* stage = sm + 8192 + wl * 2048;
    uint32_t* fragA = (uint32_t*)frag;
    uint32_t* fragB = (uint32_t*)(frag + 512);
    float* smf = frag;

    int jc = j & 7;
    int jr = j >> 3;
    int permj = (j >> 2) + (j & 3) * 8;
    int nw = gridDim.x * 8;

    int u = blockIdx.x * 8 + wl;
    int s = 0, e = 0;
    float pj = 0.f;
    int s2 = 0, e2 = 0;
    float pj2 = 0.f;

    if (u < n_nodes) {
        s = g_off[u]; e = g_off[u + 1];
        pj = g_P[(size_t)u * 32 + j];
        int vc = (s + j < e) ? g_csr[s + j] : 0;
        int cnt0 = min(32, e - s);
#pragma unroll
        for (int k = 0; k < 8; k++) {
            int row = jr + 4 * k;
            int vv = __shfl_sync(0xffffffffu, vc, row);
            if (row < cnt0) {
                uint32_t d = (uint32_t)__cvta_generic_to_shared(
                    stage + row * 32 + ((jc ^ (row & 7)) << 2));
                cpasync16(d, &g_Q[(size_t)vv * 32 + jc * 4]);
            }
        }
        cpasync_commit();
        int u2 = u + nw;
        if (u2 < n_nodes) {
            s2 = g_off[u2]; e2 = g_off[u2 + 1];
            pj2 = g_P[(size_t)u2 * 32 + j];
        }
    }

    int ib = 0;
    for (; u < n_nodes; u += nw, ib ^= 1) {
        int u2 = u + nw;
        if (u2 < n_nodes) {
            int vc2 = (s2 + j < e2) ? g_csr[s2 + j] : 0;
            float* stg1 = stage + (ib ^ 1) * 1024;
            int cnt0 = min(32, e2 - s2);
#pragma unroll
            for (int k = 0; k < 8; k++) {
                int row = jr + 4 * k;
                int vv = __shfl_sync(0xffffffffu, vc2, row);
                if (row < cnt0) {
                    uint32_t d = (uint32_t)__cvta_generic_to_shared(
                        stg1 + row * 32 + ((jc ^ (row & 7)) << 2));
                    cpasync16(d, &g_Q[(size_t)vv * 32 + jc * 4]);
                }
            }
            cpasync_commit();
        }
        int u3 = u + 2 * nw;
        int s3 = 0, e3 = 0;
        float pj3 = 0.f;
        if (u3 < n_nodes) {
            s3 = g_off[u3]; e3 = g_off[u3 + 1];
            pj3 = g_P[(size_t)u3 * 32 + j];
        }
        if (u2 < n_nodes) cpasync_wait1(); else cpasync_wait0();
        __syncwarp();

        float4 pq4;
        pq4.x = __shfl_sync(0xffffffffu, pj, jc * 4 + 0);
        pq4.y = __shfl_sync(0xffffffffu, pj, jc * 4 + 1);
        pq4.z = __shfl_sync(0xffffffffu, pj, jc * 4 + 2);
        pq4.w = __shfl_sync(0xffffffffu, pj, jc * 4 + 3);

        float acc[8];
#pragma unroll
        for (int r = 0; r < 8; r++) acc[r] = 0.f;

        int deg = e - s;
        float* stg = stage + ib * 1024;
        int vd = (s + 32 + j < e) ? g_csr[s + 32 + j] : 0;

        if (deg > 0) {
            int cnt = min(32, deg);
            bool hasB = cnt > 16;
#pragma unroll
            for (int k = 0; k < 4; k++) {
                int row16 = jr + 4 * k;
                float4 q = *(const float4*)&stg[row16 * 32 + ((jc ^ (row16 & 7)) << 2)];
                frag_store(fragA, row16, jc, pq4, q, row16 < cnt);
            }
            if (hasB) {
#pragma unroll
                for (int k = 0; k < 4; k++) {
                    int row16 = jr + 4 * k;
                    int prow = 16 + row16;
                    float4 q = *(const float4*)&stg[prow * 32 + ((jc ^ (prow & 7)) << 2)];
                    frag_store(fragB, row16, jc, pq4, q, prow < cnt);
                }
            }
            __syncwarp();
            pass2_tile(fragA, permj, B0, B1, b2e, b2o, acc);
            if (hasB) pass2_tile(fragB, permj, B0, B1, b2e, b2o, acc);

            for (int base = s + 32; base < e; base += 32) {
                int cnt2 = min(32, e - base);
                int vdn = (base + 32 + j < e) ? g_csr[base + 32 + j] : 0;
                bool hB2 = cnt2 > 16;
                __syncwarp();
#pragma unroll
                for (int k = 0; k < 4; k++) {
                    int row = jr + 4 * k;
                    int vv = __shfl_sync(0xffffffffu, vd, row);
                    float4 q = *(const float4*)&g_Q[(size_t)vv * 32 + jc * 4];
                    frag_store(fragA, row, jc, pq4, q, row < cnt2);
                }
                if (hB2) {
#pragma unroll
                    for (int k = 4; k < 8; k++) {
                        int row = jr + 4 * k;
                        int vv = __shfl_sync(0xffffffffu, vd, row);
                        float4 q = *(const float4*)&g_Q[(size_t)vv * 32 + jc * 4];
                        frag_store(fragB, row - 16, jc, pq4, q, row < cnt2);
                    }
                }
                __syncwarp();
                pass2_tile(fragA, permj, B0, B1, b2e, b2o, acc);
                if (hB2) pass2_tile(fragB, permj, B0, B1, b2e, b2o, acc);
                vd = vdn;
            }
        }

#pragma unroll
        for (int o = 4; o < 32; o <<= 1)
#pragma unroll
            for (int r = 0; r < 8; r++)
                acc[r] += __shfl_xor_sync(0xffffffffu, acc[r], o);
        __syncwarp();
#pragma unroll
        for (int r = 0; r < 8; r++) smf[r * 32 + j] = acc[r];
        __syncwarp();
        float accj = smf[(((j >> 3) << 1) + (j & 1)) * 32 + ((j & 7) >> 1)];

        int pad = ((deg + 15) & ~15) - deg;
        accj -= (float)pad * fmaxf(bb2, 0.f);

        g_a[(size_t)u * 32 + j] = accj;
        __syncwarp();

        s = s2; e = e2; pj = pj2;
        s2 = s3; e2 = e3; pj2 = pj3;
    }
}

// ---------------- fused epilogue: node-per-thread, gi = Wf@S (no a[]) ----
// State: S[32], h[32], nh[32] = 96 floats -> no spills at 352thr (~186 regs).
__global__ void __launch_bounds__(352, 1) gru_kernel(
        const float* __restrict__ W1, const float* __restrict__ b1,
        const float* __restrict__ Whh,
        const float* __restrict__ bih, const float* __restrict__ bhh,
        float* __restrict__ out, int write_pq, int n_nodes) {
    __shared__ float sWf[96 * 32];
    __shared__ float sWhh[96 * 32];
    __shared__ float sW1[64 * 32];   // rows 0..31 = W1a, 32..63 = W1b
    __shared__ float sbi[96], sbf[96], sbhh[96], sb1[32];
    int tid = threadIdx.x;
    for (int i = tid; i < 96 * 32; i += 352) { sWf[i] = g_Wf[i]; sWhh[i] = Whh[i]; }
    for (int i = tid; i < 32 * 32; i += 352) {
        sW1[i] = W1[(i >> 5) * 67 + (i & 31)];
        sW1[1024 + i] = W1[(i >> 5) * 67 + 32 + (i & 31)];
    }
    if (tid < 96) { sbi[tid] = bih[tid]; sbf[tid] = g_bf[tid]; sbhh[tid] = bhh[tid]; }
    if (tid < 32) sb1[tid] = b1[tid];
    __syncthreads();

    int u = blockIdx.x * 352 + tid;
    if (u >= n_nodes) return;

    float S[32];
    {
        const float4* Sg = (const float4*)&g_a[(size_t)u * 32];
#pragma unroll
        for (int c = 0; c < 8; c++) {
            float4 v = Sg[c];
            S[c * 4] = v.x; S[c * 4 + 1] = v.y; S[c * 4 + 2] = v.z; S[c * 4 + 3] = v.w;
        }
    }
    float deg = (float)(g_off[u + 1] - g_off[u]);

    float h[32];
    {
        const float4* Hg = (const float4*)&g_node[(size_t)u * 32];
#pragma unroll
        for (int c = 0; c < 8; c++) {
            float4 v = Hg[c];
            h[c * 4] = v.x; h[c * 4 + 1] = v.y; h[c * 4 + 2] = v.z; h[c * 4 + 3] = v.w;
        }
    }

    float nh[32];
    for (int o = 0; o < 32; o++) {
        const float4* wr = (const float4*)&sWf[o * 32];
        const float4* wz = (const float4*)&sWf[(o + 32) * 32];
        const float4* wn = (const float4*)&sWf[(o + 64) * 32];
        const float4* vr = (const float4*)&sWhh[o * 32];
        const float4* vz = (const float4*)&sWhh[(o + 32) * 32];
        const float4* vn = (const float4*)&sWhh[(o + 64) * 32];
        float gir = fmaf(deg, sbf[o],      sbi[o]);
        float giz = fmaf(deg, sbf[o + 32], sbi[o + 32]);
        float gin = fmaf(deg, sbf[o + 64], sbi[o + 64]);
        float ghr = sbhh[o], ghz = sbhh[o + 32], ghn = sbhh[o + 64];
#pragma unroll
        for (int c = 0; c < 8; c++) {
            float a0 = S[4 * c], a1 = S[4 * c + 1], a2 = S[4 * c + 2], a3 = S[4 * c + 3];
            float h0 = h[4 * c], h1 = h[4 * c + 1], h2 = h[4 * c + 2], h3 = h[4 * c + 3];
            float4 w;
            w = wr[c]; gir = fmaf(w.x, a0, gir); gir = fmaf(w.y, a1, gir);
                       gir = fmaf(w.z, a2, gir); gir = fmaf(w.w, a3, gir);
            w = wz[c]; giz = fmaf(w.x, a0, giz); giz = fmaf(w.y, a1, giz);
                       giz = fmaf(w.z, a2, giz); giz = fmaf(w.w, a3, giz);
            w = wn[c]; gin = fmaf(w.x, a0, gin); gin = fmaf(w.y, a1, gin);
                       gin = fmaf(w.z, a2, gin); gin = fmaf(w.w, a3, gin);
            w = vr[c]; ghr = fmaf(w.x, h0, ghr); ghr = fmaf(w.y, h1, ghr);
                       ghr = fmaf(w.z, h2, ghr); ghr = fmaf(w.w, h3, ghr);
            w = vz[c]; ghz = fmaf(w.x, h0, ghz); ghz = fmaf(w.y, h1, ghz);
                       ghz = fmaf(w.z, h2, ghz); ghz = fmaf(w.w, h3, ghz);
            w = vn[c]; ghn = fmaf(w.x, h0, ghn); ghn = fmaf(w.y, h1, ghn);
                       ghn = fmaf(w.z, h2, ghn); ghn = fmaf(w.w, h3, ghn);
        }
        float r = sigf(gir + ghr);
        float z = sigf(giz + ghz);
        float nv = tanhfast(gin + r * ghn);
        nh[o] = (1.f - z) * nv + z * h[o];
    }

    {
        float4* Ng = (float4*)&g_node[(size_t)u * 32];
#pragma unroll
        for (int c = 0; c < 8; c++)
            Ng[c] = make_float4(nh[4 * c], nh[4 * c + 1], nh[4 * c + 2], nh[4 * c + 3]);
        if (out) {
            float4* Og = (float4*)&out[(size_t)u * 32];
#pragma unroll
            for (int c = 0; c < 8; c++)
                Og[c] = make_float4(nh[4 * c], nh[4 * c + 1], nh[4 * c + 2], nh[4 * c + 3]);
        }
    }

    if (write_pq) {
        const float4* Vg = (const float4*)&g_pvc[(size_t)u * 32];
        float4* Pg = (float4*)&g_P[(size_t)u * 32];
        float4* Qg = (float4*)&g_Q[(size_t)u * 32];
        for (int cb = 0; cb < 8; cb++) {
            float4 pv = Vg[cb];
            float pr[4], qr[4];
#pragma unroll
            for (int t = 0; t < 4; t++) {
                int jj = cb * 4 + t;
                const float4* wa = (const float4*)&sW1[jj * 32];
                const float4* wb = (const float4*)&sW1[(jj + 32) * 32];
                float p = 0.f, q = 0.f;
#pragma unroll
                for (int c = 0; c < 8; c++) {
                    float4 w1a = wa[c], w1b = wb[c];
                    p = fmaf(w1a.x, nh[4 * c], p);     p = fmaf(w1a.y, nh[4 * c + 1], p);
                    p = fmaf(w1a.z, nh[4 * c + 2], p); p = fmaf(w1a.w, nh[4 * c + 3], p);
                    q = fmaf(w1b.x, nh[4 * c], q);     q = fmaf(w1b.y, nh[4 * c + 1], q);
                    q = fmaf(w1b.z, nh[4 * c + 2], q); q = fmaf(w1b.w, nh[4 * c + 3], q);
                }
                pr[t] = p + sb1[jj];
                qr[t] = q;
            }
            Pg[cb] = make_float4(pr[0] - pv.x, pr[1] - pv.y, pr[2] - pv.z, pr[3] - pv.w);
            Qg[cb] = make_float4(qr[0] + pv.x, qr[1] + pv.y, qr[2] + pv.z, qr[3] + pv.w);
        }
    }
}

// ---------------- launch ----------------
extern "C" void kernel_launch(void* const* d_in, const int* in_sizes, int n_in,
                              void* d_out, int out_size) {
    const float* pos     = (const float*)d_in[0];
    const float* classes = (const float*)d_in[1];
    const int*   edges   = (const int*)d_in[2];
    int wb = (in_sizes[3] == 1) ? 4 : 3;
    const float* Win = (const float*)d_in[wb + 0];
    const float* bin = (const float*)d_in[wb + 1];
    const float* W1  = (const float*)d_in[wb + 2];
    const float* b1  = (const float*)d_in[wb + 3];
    const float* W2  = (const float*)d_in[wb + 4];
    const float* b2  = (const float*)d_in[wb + 5];
    const float* W3  = (const float*)d_in[wb + 6];
    const float* b3  = (const float*)d_in[wb + 7];
    const float* Wih = (const float*)d_in[wb + 8];
    const float* Whh = (const float*)d_in[wb + 9];
    const float* bih = (const float*)d_in[wb + 10];
    const float* bhh = (const float*)d_in[wb + 11];

    int n_nodes = in_sizes[0] / 3;
    int n_edges = in_sizes[2] / 2;
    int n2e = 2 * n_edges;
    float* out = (float*)d_out;
    int seg = (n_nodes + NB - 1) / NB;

    cudaFuncSetAttribute(edge_kernel,
                         cudaFuncAttributeMaxDynamicSharedMemorySize,
                         EDGE_SMEM_BYTES);

    count_kernel<<<(n2e + 255) / 256, 256>>>(edges, n2e);
    scan1_kernel<<<NB, 256>>>(n_nodes, seg);
    scan23_kernel<<<NB, 256>>>(n_nodes, seg);
    scatter_kernel<<<(n2e + 255) / 256, 256>>>(edges, n_edges);
    wf_kernel<<<12, 256>>>(Wih, W3, b3);
    embed_pq_kernel<<<(n_nodes + 7) / 8, 256>>>(classes, pos, Win, bin, W1, b1,
                                                n_nodes);

    int gru_grid = (n_nodes + 351) / 352;
    for (int it = 0; it < 6; ++it) {
        edge_kernel<<<296, 256, EDGE_SMEM_BYTES>>>(W2, b2, n_nodes);
        gru_kernel<<<gru_grid, 352>>>(
            W1, b1, Whh, bih, bhh,
            (it == 5) ? out : (float*)nullptr, (it < 5) ? 1 : 0, n_nodes);
    }
}

// round 15
// speedup vs baseline: 1.3093x; 1.0008x over previous
#include <cuda_runtime.h>
#include <cstdint>

#define NN 50000
#define NE 800000
#define NB 64

// ---------------- scratch (device globals: allocation-free) ----------------
__device__ __align__(16) float g_node[NN * 32];
__device__ __align__(16) float g_P[NN * 32];
__device__ __align__(16) float g_Q[NN * 32];
__device__ __align__(16) float g_pvc[NN * 32];
__device__ __align__(16) float g_a[NN * 32];
__device__ __align__(16) float g_Wf[96 * 32];   // Wih @ W3 (fused)
__device__ float g_bf[96];                       // Wih @ b3
__device__ int   g_cnt[NN];     // zero-init at load; re-zeroed by scan_lb each run
__device__ int   g_off[NN + 1];
__device__ int   g_cur[NN];
__device__ int   g_csr[2 * NE];
__device__ int   g_bsum[NB];
__device__ int   g_bflag[NB];   // lookback flags; reset by scatter_embed each run

// ---------------- helpers ----------------
__device__ __forceinline__ uint32_t tf32c(float x) {
    uint32_t r;
    asm("cvt.rna.tf32.f32 %0, %1;" : "=r"(r) : "f"(x));
    return r;
}
__device__ __forceinline__ void mma_tf32(float& d0, float& d1, float& d2, float& d3,
                                         uint32_t a0, uint32_t a1, uint32_t a2, uint32_t a3,
                                         uint32_t b0, uint32_t b1) {
    asm("mma.sync.aligned.m16n8k8.row.col.f32.tf32.tf32.f32 "
        "{%0,%1,%2,%3}, {%4,%5,%6,%7}, {%8,%9}, {%0,%1,%2,%3};"
        : "+f"(d0), "+f"(d1), "+f"(d2), "+f"(d3)
        : "r"(a0), "r"(a1), "r"(a2), "r"(a3), "r"(b0), "r"(b1));
}
__device__ __forceinline__ float sigf(float x) {
    return __fdividef(1.f, 1.f + __expf(-x));
}
__device__ __forceinline__ float tanhfast(float x) {
    float ex = __expf(2.f * x);
    return 1.f - __fdividef(2.f, ex + 1.f);
}
__device__ __forceinline__ void cpasync16(uint32_t dst_s, const void* src) {
    asm volatile("cp.async.cg.shared.global [%0], [%1], 16;"
                 :: "r"(dst_s), "l"(src));
}
__device__ __forceinline__ void cpasync_commit() {
    asm volatile("cp.async.commit_group;" ::: "memory");
}
__device__ __forceinline__ void cpasync_wait0() {
    asm volatile("cp.async.wait_group 0;" ::: "memory");
}
__device__ __forceinline__ void cpasync_wait1() {
    asm volatile("cp.async.wait_group 1;" ::: "memory");
}

// fragment store of one relu'd float4 (verified layout, rounds 8-14)
__device__ __forceinline__ void frag_store(uint32_t* fragT, int row16, int jc,
                                           float4 pq4, float4 q, bool valid) {
    float h0 = fmaxf(pq4.x + q.x, 0.f);
    float h1 = fmaxf(pq4.y + q.y, 0.f);
    float h2 = fmaxf(pq4.z + q.z, 0.f);
    float h3 = fmaxf(pq4.w + q.w, 0.f);
    if (!valid) { h0 = h1 = h2 = h3 = 0.f; }
    int T0 = ((row16 >> 3) & 1) + (jc << 1);
    int bA = T0 * 32;
    int sw = (row16 & 7) + 2 * T0;
    fragT[bA + ((sw     ) & 31)] = tf32c(h0);
    fragT[bA + ((sw +  8) & 31)] = tf32c(h1);
    fragT[bA + ((sw + 16) & 31)] = tf32c(h2);
    fragT[bA + ((sw + 24) & 31)] = tf32c(h3);
}

__device__ __forceinline__ void pass2_tile(const uint32_t* fragT, int permj,
                                           const uint32_t* B0, const uint32_t* B1,
                                           const float* b2e, const float* b2o,
                                           float* acc) {
    uint32_t a[16];
#pragma unroll
    for (int idx = 0; idx < 16; idx++)
        a[idx] = fragT[idx * 32 + ((permj + 2 * idx) & 31)];
#pragma unroll
    for (int nt = 0; nt < 4; nt++) {
        float d0 = 0.f, d1 = 0.f, d2 = 0.f, d3 = 0.f;
#pragma unroll
        for (int kt = 0; kt < 4; kt++)
            mma_tf32(d0, d1, d2, d3,
                     a[kt * 4 + 0], a[kt * 4 + 1], a[kt * 4 + 2], a[kt * 4 + 3],
                     B0[kt * 4 + nt], B1[kt * 4 + nt]);
        acc[nt * 2 + 0] += fmaxf(d0 + b2e[nt], 0.f) + fmaxf(d2 + b2e[nt], 0.f);
        acc[nt * 2 + 1] += fmaxf(d1 + b2o[nt], 0.f) + fmaxf(d3 + b2o[nt], 0.f);
    }
}

// ---------------- prep kernel 1: degree count ----------------
__global__ void count_kernel(const int* __restrict__ e, int n2e) {
    int i = blockIdx.x * blockDim.x + threadIdx.x;
    if (i < n2e) atomicAdd(&g_cnt[e[i]], 1);
}

// ---------------- prep kernel 2: decoupled-lookback scan + wf ----------
// Blocks 0..NB-1: scan g_cnt -> g_off/g_cur (and zero g_cnt for replay).
// Block NB: Wf = Wih@W3, bf = Wih@b3.
__global__ void scan_lb_kernel(const float* __restrict__ Wih,
                               const float* __restrict__ W3,
                               const float* __restrict__ b3,
                               int n, int seg) {
    int b = blockIdx.x, tid = threadIdx.x;
    if (b == NB) {   // fused wf
        for (int idx = tid; idx < 96 * 32; idx += 256) {
            int g = idx >> 5, k = idx & 31;
            float s = 0.f;
#pragma unroll
            for (int o = 0; o < 32; o++)
                s = fmaf(Wih[g * 32 + o], W3[o * 32 + k], s);
            g_Wf[idx] = s;
        }
        if (tid < 96) {
            float s = 0.f;
#pragma unroll
            for (int o = 0; o < 32; o++)
                s = fmaf(Wih[tid * 32 + o], b3[o], s);
            g_bf[tid] = s;
        }
        return;
    }

    int beg = b * seg, end = min(beg + seg, n);
    int len = max(end - beg, 0);
    int c = (len + 255) / 256;
    int tb = min(beg + tid * c, end), te = min(tb + c, end);
    int s = 0;
    for (int i = tb; i < te; i++) s += g_cnt[i];
    int lane = tid & 31, w = tid >> 5;
    int v = s;
#pragma unroll
    for (int o = 1; o < 32; o <<= 1) {
        int t = __shfl_up_sync(0xffffffffu, v, o);
        if (lane >= o) v += t;
    }
    __shared__ int wt[8], wpre[8];
    __shared__ int s_pre;
    if (lane == 31) wt[w] = v;
    if (tid == 0) s_pre = 0;
    __syncthreads();
    if (tid < 8) {
        int x = wt[tid];
#pragma unroll
        for (int o = 1; o < 8; o <<= 1) {
            int t = __shfl_up_sync(0xffu, x, o);
            if (tid >= o) x += t;
        }
        wpre[tid] = x;
    }
    __syncthreads();

    // publish block aggregate (release), then look back at predecessors
    if (tid == 0) {
        g_bsum[b] = wpre[7];
        __threadfence();
        atomicExch(&g_bflag[b], 1);
    }
    if (tid < b) {   // b <= 63 < 256: one thread per predecessor
        while (atomicAdd(&g_bflag[tid], 0) == 0) {}
        __threadfence();
        atomicAdd(&s_pre, g_bsum[tid]);
    }
    __syncthreads();

    int excl = (v - s) + (w > 0 ? wpre[w - 1] : 0);
    int run = s_pre + excl;
    for (int i = tb; i < te; i++) {
        g_off[i] = run;
        g_cur[i] = run;
        run += g_cnt[i];
    }
    for (int i = tb; i < te; i++) g_cnt[i] = 0;   // ready for next replay
    if (b == NB - 1 && tid == 255) g_off[n] = run;
}

// ---------------- prep kernel 3: scatter + embed (independent, fused) ----
// Blocks [0, nsb): CSR scatter. Blocks [nsb, ...): embed/pvc/P0/Q0.
// Also resets lookback flags for the next replay.
__global__ void scatter_embed_kernel(const int* __restrict__ e, int nE,
                                     const float* __restrict__ classes,
                                     const float* __restrict__ pos,
                                     const float* __restrict__ Win,
                                     const float* __restrict__ bin,
                                     const float* __restrict__ W1,
                                     const float* __restrict__ b1,
                                     int n_nodes, int nsb) {
    if (blockIdx.x == 0 && threadIdx.x < NB) g_bflag[threadIdx.x] = 0;

    if (blockIdx.x < nsb) {
        int i = blockIdx.x * blockDim.x + threadIdx.x;
        if (i >= 2 * nE) return;
        int src = e[i];
        int dst = (i < nE) ? e[i + nE] : e[i - nE];
        int slot = atomicAdd(&g_cur[src], 1);
        g_csr[slot] = dst;
        return;
    }

    int warp = ((blockIdx.x - nsb) * blockDim.x + threadIdx.x) >> 5;
    int j = threadIdx.x & 31;
    if (warp >= n_nodes) return;
    int u = warp;

    float w[16];
#pragma unroll
    for (int k = 0; k < 16; k++) w[k] = Win[j * 16 + k];
    float c = (j < 16) ? classes[u * 16 + j] : 0.f;
    float acc = bin[j];
#pragma unroll
    for (int k = 0; k < 16; k++)
        acc = fmaf(w[k], __shfl_sync(0xffffffffu, c, k), acc);
    g_node[u * 32 + j] = acc;

    float p0 = pos[u * 3 + 0], p1 = pos[u * 3 + 1], p2 = pos[u * 3 + 2];
    float pv = p0 * W1[j * 67 + 64] + p1 * W1[j * 67 + 65] + p2 * W1[j * 67 + 66];
    g_pvc[u * 32 + j] = pv;

    float p = 0.f, q = 0.f;
#pragma unroll
    for (int k = 0; k < 32; k++) {
        float val = __shfl_sync(0xffffffffu, acc, k);
        p = fmaf(W1[j * 67 + k], val, p);
        q = fmaf(W1[j * 67 + 32 + k], val, q);
    }
    g_P[u * 32 + j] = p + b1[j] - pv;
    g_Q[u * 32 + j] = q + pv;
}

// ---------------- message-pass kernel (unchanged from round 14) ----------
#define EDGE_SMEM_BYTES (24576 * 4)

__global__ void __launch_bounds__(256, 2) edge_kernel(
        const float* __restrict__ W2, const float* __restrict__ b2,
        int n_nodes) {
    extern __shared__ float sm[];
    int tid = threadIdx.x, wl = tid >> 5, j = tid & 31;

    uint32_t B0[16], B1[16];
#pragma unroll
    for (int kt = 0; kt < 4; kt++)
#pragma unroll
        for (int nt = 0; nt < 4; nt++) {
            int ncol = nt * 8 + (j >> 2);
            int krow = kt * 8 + (j & 3);
            B0[kt * 4 + nt] = tf32c(W2[ncol * 32 + krow]);
            B1[kt * 4 + nt] = tf32c(W2[ncol * 32 + krow + 4]);
        }
    float b2e[4], b2o[4];
#pragma unroll
    for (int nt = 0; nt < 4; nt++) {
        b2e[nt] = b2[nt * 8 + (j & 3) * 2];
        b2o[nt] = b2[nt * 8 + (j & 3) * 2 + 1];
    }
    float bb2 = b2[j];

    float* frag  = sm + wl * 1024;
    float* stage = sm + 8192 + wl * 2048;
    uint32_t* fragA = (uint32_t*)frag;
    uint32_t* fragB = (uint32_t*)(frag + 512);
    float* smf = frag;

    int jc = j & 7;
    int jr = j >> 3;
    int permj = (j >> 2) + (j & 3) * 8;
    int nw = gridDim.x * 8;

    int u = blockIdx.x * 8 + wl;
    int s = 0, e = 0;
    float pj = 0.f;
    int s2 = 0, e2 = 0;
    float pj2 = 0.f;

    if (u < n_nodes) {
        s = g_off[u]; e = g_off[u + 1];
        pj = g_P[(size_t)u * 32 + j];
        int vc = (s + j < e) ? g_csr[s + j] : 0;
        int cnt0 = min(32, e - s);
#pragma unroll
        for (int k = 0; k < 8; k++) {
            int row = jr + 4 * k;
            int vv = __shfl_sync(0xffffffffu, vc, row);
            if (row < cnt0) {
                uint32_t d = (uint32_t)__cvta_generic_to_shared(
                    stage + row * 32 + ((jc ^ (row & 7)) << 2));
                cpasync16(d, &g_Q[(size_t)vv * 32 + jc * 4]);
            }
        }
        cpasync_commit();
        int u2 = u + nw;
        if (u2 < n_nodes) {
            s2 = g_off[u2]; e2 = g_off[u2 + 1];
            pj2 = g_P[(size_t)u2 * 32 + j];
        }
    }

    int ib = 0;
    for (; u < n_nodes; u += nw, ib ^= 1) {
        int u2 = u + nw;
        if (u2 < n_nodes) {
            int vc2 = (s2 + j < e2) ? g_csr[s2 + j] : 0;
            float* stg1 = stage + (ib ^ 1) * 1024;
            int cnt0 = min(32, e2 - s2);
#pragma unroll
            for (int k = 0; k < 8; k++) {
                int row = jr + 4 * k;
                int vv = __shfl_sync(0xffffffffu, vc2, row);
                if (row < cnt0) {
                    uint32_t d = (uint32_t)__cvta_generic_to_shared(
                        stg1 + row * 32 + ((jc ^ (row & 7)) << 2));
                    cpasync16(d, &g_Q[(size_t)vv * 32 + jc * 4]);
                }
            }
            cpasync_commit();
        }
        int u3 = u + 2 * nw;
        int s3 = 0, e3 = 0;
        float pj3 = 0.f;
        if (u3 < n_nodes) {
            s3 = g_off[u3]; e3 = g_off[u3 + 1];
            pj3 = g_P[(size_t)u3 * 32 + j];
        }
        if (u2 < n_nodes) cpasync_wait1(); else cpasync_wait0();
        __syncwarp();

        float4 pq4;
        pq4.x = __shfl_sync(0xffffffffu, pj, jc * 4 + 0);
        pq4.y = __shfl_sync(0xffffffffu, pj, jc * 4 + 1);
        pq4.z = __shfl_sync(0xffffffffu, pj, jc * 4 + 2);
        pq4.w = __shfl_sync(0xffffffffu, pj, jc * 4 + 3);

        float acc[8];
#pragma unroll
        for (int r = 0; r < 8; r++) acc[r] = 0.f;

        int deg = e - s;
        float* stg = stage + ib * 1024;
        int vd = (s + 32 + j < e) ? g_csr[s + 32 + j] : 0;

        if (deg > 0) {
            int cnt = min(32, deg);
            bool hasB = cnt > 16;
#pragma unroll
            for (int k = 0; k < 4; k++) {
                int row16 = jr + 4 * k;
                float4 q = *(const float4*)&stg[row16 * 32 + ((jc ^ (row16 & 7)) << 2)];
                frag_store(fragA, row16, jc, pq4, q, row16 < cnt);
            }
            if (hasB) {
#pragma unroll
                for (int k = 0; k < 4; k++) {
                    int row16 = jr + 4 * k;
                    int prow = 16 + row16;
                    float4 q = *(const float4*)&stg[prow * 32 + ((jc ^ (prow & 7)) << 2)];
                    frag_store(fragB, row16, jc, pq4, q, prow < cnt);
                }
            }
            __syncwarp();
            pass2_tile(fragA, permj, B0, B1, b2e, b2o, acc);
            if (hasB) pass2_tile(fragB, permj, B0, B1, b2e, b2o, acc);

            for (int base = s + 32; base < e; base += 32) {
                int cnt2 = min(32, e - base);
                int vdn = (base + 32 + j < e) ? g_csr[base + 32 + j] : 0;
                bool hB2 = cnt2 > 16;
                __syncwarp();
#pragma unroll
                for (int k = 0; k < 4; k++) {
                    int row = jr + 4 * k;
                    int vv = __shfl_sync(0xffffffffu, vd, row);
                    float4 q = *(const float4*)&g_Q[(size_t)vv * 32 + jc * 4];
                    frag_store(fragA, row, jc, pq4, q, row < cnt2);
                }
                if (hB2) {
#pragma unroll
                    for (int k = 4; k < 8; k++) {
                        int row = jr + 4 * k;
                        int vv = __shfl_sync(0xffffffffu, vd, row);
                        float4 q = *(const float4*)&g_Q[(size_t)vv * 32 + jc * 4];
                        frag_store(fragB, row - 16, jc, pq4, q, row < cnt2);
                    }
                }
                __syncwarp();
                pass2_tile(fragA, permj, B0, B1, b2e, b2o, acc);
                if (hB2) pass2_tile(fragB, permj, B0, B1, b2e, b2o, acc);
                vd = vdn;
            }
        }

#pragma unroll
        for (int o = 4; o < 32; o <<= 1)
#pragma unroll
            for (int r = 0; r < 8; r++)
                acc[r] += __shfl_xor_sync(0xffffffffu, acc[r], o);
        __syncwarp();
#pragma unroll
        for (int r = 0; r < 8; r++) smf[r * 32 + j] = acc[r];
        __syncwarp();
        float accj = smf[(((j >> 3) << 1) + (j & 1)) * 32 + ((j & 7) >> 1)];

        int pad = ((deg + 15) & ~15) - deg;
        accj -= (float)pad * fmaxf(bb2, 0.f);

        g_a[(size_t)u * 32 + j] = accj;
        __syncwarp();

        s = s2; e = e2; pj = pj2;
        s2 = s3; e2 = e3; pj2 = pj3;
    }
}

// ---------------- fused epilogue: node-per-thread (round-14) ----------
__global__ void __launch_bounds__(352, 1) gru_kernel(
        const float* __restrict__ W1, const float* __restrict__ b1,
        const float* __restrict__ Whh,
        const float* __restrict__ bih, const float* __restrict__ bhh,
        float* __restrict__ out, int write_pq, int n_nodes) {
    __shared__ float sWf[96 * 32];
    __shared__ float sWhh[96 * 32];
    __shared__ float sW1[64 * 32];
    __shared__ float sbi[96], sbf[96], sbhh[96], sb1[32];
    int tid = threadIdx.x;
    for (int i = tid; i < 96 * 32; i += 352) { sWf[i] = g_Wf[i]; sWhh[i] = Whh[i]; }
    for (int i = tid; i < 32 * 32; i += 352) {
        sW1[i] = W1[(i >> 5) * 67 + (i & 31)];
        sW1[1024 + i] = W1[(i >> 5) * 67 + 32 + (i & 31)];
    }
    if (tid < 96) { sbi[tid] = bih[tid]; sbf[tid] = g_bf[tid]; sbhh[tid] = bhh[tid]; }
    if (tid < 32) sb1[tid] = b1[tid];
    __syncthreads();

    int u = blockIdx.x * 352 + tid;
    if (u >= n_nodes) return;

    float S[32];
    {
        const float4* Sg = (const float4*)&g_a[(size_t)u * 32];
#pragma unroll
        for (int c = 0; c < 8; c++) {
            float4 v = Sg[c];
            S[c * 4] = v.x; S[c * 4 + 1] = v.y; S[c * 4 + 2] = v.z; S[c * 4 + 3] = v.w;
        }
    }
    float deg = (float)(g_off[u + 1] - g_off[u]);

    float h[32];
    {
        const float4* Hg = (const float4*)&g_node[(size_t)u * 32];
#pragma unroll
        for (int c = 0; c < 8; c++) {
            float4 v = Hg[c];
            h[c * 4] = v.x; h[c * 4 + 1] = v.y; h[c * 4 + 2] = v.z; h[c * 4 + 3] = v.w;
        }
    }

    float nh[32];
    for (int o = 0; o < 32; o++) {
        const float4* wr = (const float4*)&sWf[o * 32];
        const float4* wz = (const float4*)&sWf[(o + 32) * 32];
        const float4* wn = (const float4*)&sWf[(o + 64) * 32];
        const float4* vr = (const float4*)&sWhh[o * 32];
        const float4* vz = (const float4*)&sWhh[(o + 32) * 32];
        const float4* vn = (const float4*)&sWhh[(o + 64) * 32];
        float gir = fmaf(deg, sbf[o],      sbi[o]);
        float giz = fmaf(deg, sbf[o + 32], sbi[o + 32]);
        float gin = fmaf(deg, sbf[o + 64], sbi[o + 64]);
        float ghr = sbhh[o], ghz = sbhh[o + 32], ghn = sbhh[o + 64];
#pragma unroll
        for (int c = 0; c < 8; c++) {
            float a0 = S[4 * c], a1 = S[4 * c + 1], a2 = S[4 * c + 2], a3 = S[4 * c + 3];
            float h0 = h[4 * c], h1 = h[4 * c + 1], h2 = h[4 * c + 2], h3 = h[4 * c + 3];
            float4 w;
            w = wr[c]; gir = fmaf(w.x, a0, gir); gir = fmaf(w.y, a1, gir);
                       gir = fmaf(w.z, a2, gir); gir = fmaf(w.w, a3, gir);
            w = wz[c]; giz = fmaf(w.x, a0, giz); giz = fmaf(w.y, a1, giz);
                       giz = fmaf(w.z, a2, giz); giz = fmaf(w.w, a3, giz);
            w = wn[c]; gin = fmaf(w.x, a0, gin); gin = fmaf(w.y, a1, gin);
                       gin = fmaf(w.z, a2, gin); gin = fmaf(w.w, a3, gin);
            w = vr[c]; ghr = fmaf(w.x, h0, ghr); ghr = fmaf(w.y, h1, ghr);
                       ghr = fmaf(w.z, h2, ghr); ghr = fmaf(w.w, h3, ghr);
            w = vz[c]; ghz = fmaf(w.x, h0, ghz); ghz = fmaf(w.y, h1, ghz);
                       ghz = fmaf(w.z, h2, ghz); ghz = fmaf(w.w, h3, ghz);
            w = vn[c]; ghn = fmaf(w.x, h0, ghn); ghn = fmaf(w.y, h1, ghn);
                       ghn = fmaf(w.z, h2, ghn); ghn = fmaf(w.w, h3, ghn);
        }
        float r = sigf(gir + ghr);
        float z = sigf(giz + ghz);
        float nv = tanhfast(gin + r * ghn);
        nh[o] = (1.f - z) * nv + z * h[o];
    }

    {
        float4* Ng = (float4*)&g_node[(size_t)u * 32];
#pragma unroll
        for (int c = 0; c < 8; c++)
            Ng[c] = make_float4(nh[4 * c], nh[4 * c + 1], nh[4 * c + 2], nh[4 * c + 3]);
        if (out) {
            float4* Og = (float4*)&out[(size_t)u * 32];
#pragma unroll
            for (int c = 0; c < 8; c++)
                Og[c] = make_float4(nh[4 * c], nh[4 * c + 1], nh[4 * c + 2], nh[4 * c + 3]);
        }
    }

    if (write_pq) {
        const float4* Vg = (const float4*)&g_pvc[(size_t)u * 32];
        float4* Pg = (float4*)&g_P[(size_t)u * 32];
        float4* Qg = (float4*)&g_Q[(size_t)u * 32];
        for (int cb = 0; cb < 8; cb++) {
            float4 pv = Vg[cb];
            float pr[4], qr[4];
#pragma unroll
            for (int t = 0; t < 4; t++) {
                int jj = cb * 4 + t;
                const float4* wa = (const float4*)&sW1[jj * 32];
                const float4* wb = (const float4*)&sW1[(jj + 32) * 32];
                float p = 0.f, q = 0.f;
#pragma unroll
                for (int c = 0; c < 8; c++) {
                    float4 w1a = wa[c], w1b = wb[c];
                    p = fmaf(w1a.x, nh[4 * c], p);     p = fmaf(w1a.y, nh[4 * c + 1], p);
                    p = fmaf(w1a.z, nh[4 * c + 2], p); p = fmaf(w1a.w, nh[4 * c + 3], p);
                    q = fmaf(w1b.x, nh[4 * c], q);     q = fmaf(w1b.y, nh[4 * c + 1], q);
                    q = fmaf(w1b.z, nh[4 * c + 2], q); q = fmaf(w1b.w, nh[4 * c + 3], q);
                }
                pr[t] = p + sb1[jj];
                qr[t] = q;
            }
            Pg[cb] = make_float4(pr[0] - pv.x, pr[1] - pv.y, pr[2] - pv.z, pr[3] - pv.w);
            Qg[cb] = make_float4(qr[0] + pv.x, qr[1] + pv.y, qr[2] + pv.z, qr[3] + pv.w);
        }
    }
}

// ---------------- launch ----------------
extern "C" void kernel_launch(void* const* d_in, const int* in_sizes, int n_in,
                              void* d_out, int out_size) {
    const float* pos     = (const float*)d_in[0];
    const float* classes = (const float*)d_in[1];
    const int*   edges   = (const int*)d_in[2];
    int wb = (in_sizes[3] == 1) ? 4 : 3;
    const float* Win = (const float*)d_in[wb + 0];
    const float* bin = (const float*)d_in[wb + 1];
    const float* W1  = (const float*)d_in[wb + 2];
    const float* b1  = (const float*)d_in[wb + 3];
    const float* W2  = (const float*)d_in[wb + 4];
    const float* b2  = (const float*)d_in[wb + 5];
    const float* W3  = (const float*)d_in[wb + 6];
    const float* b3  = (const float*)d_in[wb + 7];
    const float* Wih = (const float*)d_in[wb + 8];
    const float* Whh = (const float*)d_in[wb + 9];
    const float* bih = (const float*)d_in[wb + 10];
    const float* bhh = (const float*)d_in[wb + 11];

    int n_nodes = in_sizes[0] / 3;
    int n_edges = in_sizes[2] / 2;
    int n2e = 2 * n_edges;
    float* out = (float*)d_out;
    int seg = (n_nodes + NB - 1) / NB;

    cudaFuncSetAttribute(edge_kernel,
                         cudaFuncAttributeMaxDynamicSharedMemorySize,
                         EDGE_SMEM_BYTES);

    int nsb = (n2e + 255) / 256;                 // scatter blocks
    int neb = (n_nodes * 32 + 255) / 256;        // embed blocks (warp per node)

    count_kernel<<<nsb, 256>>>(edges, n2e);
    scan_lb_kernel<<<NB + 1, 256>>>(Wih, W3, b3, n_nodes, seg);
    scatter_embed_kernel<<<nsb + neb, 256>>>(edges, n_edges, classes, pos,
                                             Win, bin, W1, b1, n_nodes, nsb);

    int gru_grid = (n_nodes + 351) / 352;
    for (int it = 0; it < 6; ++it) {
        edge_kernel<<<296, 256, EDGE_SMEM_BYTES>>>(W2, b2, n_nodes);   // launch #4: profiled
        gru_kernel<<<gru_grid, 352>>>(
            W1, b1, Whh, bih, bhh,
            (it == 5) ? out : (float*)nullptr, (it < 5) ? 1 : 0, n_nodes);
    }
}